// round 8
// baseline (speedup 1.0000x reference)
#include <cuda_runtime.h>
#include <cstdint>
#include <math.h>

// Problem constants
#define Bn   4
#define Sn   2048
#define Dn   1024
#define Hn   16
#define DHn  64
#define BHn  (Bn * Hn)          // 64
#define Mn   (Bn * Sn)          // 8192
#define NQT  (Sn / 128)         // 16 q-tiles
#define SCALE_F 0.125f

#define OUT_ELEMS  ((size_t)Mn * Dn)            // 8,388,608
#define ATTN_ELEMS ((size_t)BHn * Sn * Sn)      // 268,435,456

// Scratch (device globals)
__device__ float g_q[Mn * Dn];            // [B,H,S,DH]
__device__ float g_k[Mn * Dn];
__device__ float g_v[Mn * Dn];
__device__ float g_ctx[Mn * Dn];          // [B,S,H*DH]
__device__ float g_attn_scratch[ATTN_ELEMS];

// ---------------------------------------------------------------------------
// PTX helpers
// ---------------------------------------------------------------------------
__device__ __forceinline__ uint32_t smem_u32(const void* p) {
    uint32_t a;
    asm("{ .reg .u64 t; cvta.to.shared.u64 t, %1; cvt.u32.u64 %0, t; }" : "=r"(a) : "l"(p));
    return a;
}
#define CP16(dst, src) \
    asm volatile("cp.async.cg.shared.global [%0], [%1], 16;" :: "r"(dst), "l"(src))
#define CP_COMMIT() asm volatile("cp.async.commit_group;")
#define CP_WAIT1()  asm volatile("cp.async.wait_group 1;")
#define CP_WAIT0()  asm volatile("cp.async.wait_group 0;")

__device__ __forceinline__ uint32_t tf32b(float f) {
    uint32_t r; asm("cvt.rna.tf32.f32 %0, %1;" : "=r"(r) : "f"(f));
    return r;
}
__device__ __forceinline__ void mma_tf32(float c[4], const uint32_t a[4], const uint32_t b[2]) {
    asm volatile(
        "mma.sync.aligned.m16n8k8.row.col.f32.tf32.tf32.f32 "
        "{%0,%1,%2,%3}, {%4,%5,%6,%7}, {%8,%9}, {%0,%1,%2,%3};"
        : "+f"(c[0]), "+f"(c[1]), "+f"(c[2]), "+f"(c[3])
        : "r"(a[0]), "r"(a[1]), "r"(a[2]), "r"(a[3]), "r"(b[0]), "r"(b[1]));
}

// ---------------------------------------------------------------------------
// tf32 mma GEMM, 2-stage pipeline, 2 CTAs/SM. QKV fused via blockIdx.z.
// ---------------------------------------------------------------------------
#define G_AST 36
#define G_BST 132
#define G_STAGE_F (128 * G_AST + 32 * G_BST)
#define GEMM_SMEM (2 * G_STAGE_F * 4)        // 70,656 bytes

__global__ __launch_bounds__(256, 2) void tf32_gemm_kernel(
    const float* __restrict__ X0, const float* __restrict__ X1, const float* __restrict__ X2,
    const float* __restrict__ W0, const float* __restrict__ W1, const float* __restrict__ W2,
    const float* __restrict__ B0, const float* __restrict__ B1, const float* __restrict__ B2,
    float* __restrict__ O0, float* __restrict__ O1, float* __restrict__ O2,
    int mode)
{
    extern __shared__ float sm[];
    const int z = blockIdx.z;
    const float* X    = (z == 0) ? X0 : (z == 1) ? X1 : X2;
    const float* W    = (z == 0) ? W0 : (z == 1) ? W1 : W2;
    const float* bias = (z == 0) ? B0 : (z == 1) ? B1 : B2;
    float* out        = (z == 0) ? O0 : (z == 1) ? O1 : O2;

    const int tid = threadIdx.x;
    const int wid = tid >> 5, lane = tid & 31;
    const int g = lane >> 2, t = lane & 3;
    const int warpM = wid & 1, warpN = wid >> 1;
    const int bm = blockIdx.y * 128, bn = blockIdx.x * 128;

    const uint32_t sbase = smem_u32(sm);

    float c[4][4][4];
#pragma unroll
    for (int i = 0; i < 4; i++)
#pragma unroll
        for (int j = 0; j < 4; j++)
#pragma unroll
            for (int k = 0; k < 4; k++) c[i][j][k] = 0.0f;

    auto issue = [&](int cidx, int buf) {
        const float* Xp = X + (size_t)bm * Dn + cidx * 32;
        const float* Wp = W + (size_t)(cidx * 32) * Dn + bn;
        uint32_t abase = sbase + buf * (G_STAGE_F * 4);
        uint32_t bbase = abase + 128 * G_AST * 4;
#pragma unroll
        for (int j = 0; j < 4; j++) {
            int ia = tid + j * 256;
            int ar = ia >> 3, ac = ia & 7;
            CP16(abase + ar * (G_AST * 4) + ac * 16, Xp + (size_t)ar * Dn + ac * 4);
            int br = ia >> 5, bc = ia & 31;
            CP16(bbase + br * (G_BST * 4) + bc * 16, Wp + (size_t)br * Dn + bc * 4);
        }
    };

    issue(0, 0); CP_COMMIT();

    const int NCH = Dn / 32;   // 32
    for (int s = 0; s < NCH; s++) {
        CP_WAIT0();
        __syncthreads();
        if (s + 1 < NCH) { issue(s + 1, (s + 1) & 1); CP_COMMIT(); }

        const float* A = sm + (s & 1) * G_STAGE_F;
        const float* B = A + 128 * G_AST;
#pragma unroll
        for (int kk = 0; kk < 32; kk += 8) {
            uint32_t af[4][4], bf[4][2];
#pragma unroll
            for (int mt = 0; mt < 4; mt++) {
                int r0 = warpM * 64 + mt * 16 + g;
                af[mt][0] = tf32b(A[r0 * G_AST + kk + t]);
                af[mt][1] = tf32b(A[(r0 + 8) * G_AST + kk + t]);
                af[mt][2] = tf32b(A[r0 * G_AST + kk + t + 4]);
                af[mt][3] = tf32b(A[(r0 + 8) * G_AST + kk + t + 4]);
            }
#pragma unroll
            for (int nt = 0; nt < 4; nt++) {
                int n0 = warpN * 32 + nt * 8 + g;
                bf[nt][0] = tf32b(B[(kk + t) * G_BST + n0]);
                bf[nt][1] = tf32b(B[(kk + t + 4) * G_BST + n0]);
            }
#pragma unroll
            for (int mt = 0; mt < 4; mt++)
#pragma unroll
                for (int nt = 0; nt < 4; nt++)
                    mma_tf32(c[mt][nt], af[mt], bf[nt]);
        }
    }

#pragma unroll
    for (int mt = 0; mt < 4; mt++) {
#pragma unroll
        for (int nt = 0; nt < 4; nt++) {
            int m0 = bm + warpM * 64 + mt * 16 + g;
            int n0 = bn + warpN * 32 + nt * 8 + 2 * t;
#pragma unroll
            for (int half = 0; half < 2; half++) {
                int m = m0 + half * 8;
                float v0 = c[mt][nt][half * 2 + 0] + bias[n0];
                float v1 = c[mt][nt][half * 2 + 1] + bias[n0 + 1];
                if (mode == 0) {
                    out[(size_t)m * Dn + n0] = v0;
                    out[(size_t)m * Dn + n0 + 1] = v1;
                } else {
                    int b = m >> 11, sq = m & (Sn - 1);
                    int h = n0 >> 6, d = n0 & 63;
                    size_t base = (((size_t)b * Hn + h) * Sn + sq) * DHn + d;
                    out[base] = v0;
                    out[base + 1] = v1;
                }
            }
        }
    }
}

// ---------------------------------------------------------------------------
// Fused attention, 2 CTAs/SM (105.5 KB smem).
// Phase 1: row sums of exp(QK^T), K ping-pong in bufs A/B.
// Phase 2: K in A, V in B; V-load overlaps S-mma, K(c+1)-load overlaps exp.
// ---------------------------------------------------------------------------
#define F_ST   68
#define F_Q    0                          // 128 x 68
#define F_A    (128 * F_ST)               // 64 x 68
#define F_B    (F_A + 64 * F_ST)          // 64 x 68
#define F_P    (F_B + 64 * F_ST)          // 128 x 68
#define F_L    (F_P + 128 * F_ST)         // 128
#define F_INV  (F_L + 128)                // 128
#define FUSED_SMEM ((F_INV + 128) * 4)    // 105,472 bytes

__global__ __launch_bounds__(256, 2) void fused_attn_kernel(
    const float* __restrict__ q, const float* __restrict__ k,
    const float* __restrict__ v, float* __restrict__ attn,
    float* __restrict__ ctx)
{
    extern __shared__ float sm[];
    const int bh = blockIdx.y;
    const int qt = (NQT - 1) - blockIdx.x;   // heavy tiles first
    const int b = bh >> 4, h = bh & 15;

    const int tid = threadIdx.x;
    const int wid = tid >> 5, lane = tid & 31;
    const int g = lane >> 2, t = lane & 3;
    const int warpM = wid & 1, warpN = wid >> 1;   // 2 x 4

    const uint32_t sbase = smem_u32(sm);
    const float* qb = q + ((size_t)bh * Sn + qt * 128) * DHn;
    const float* kbase = k + (size_t)bh * Sn * DHn;
    const float* vbase = v + (size_t)bh * Sn * DHn;
    float* attn_base = attn + ((size_t)bh * Sn + qt * 128) * Sn;

    const int ntiles = 2 * (qt + 1);   // 64-row K/V tiles

    auto issueK = [&](int c, uint32_t bufoff) {
        const float* kb = kbase + (size_t)(c * 64) * DHn;
        uint32_t dst = sbase + bufoff * 4;
#pragma unroll
        for (int j = 0; j < 4; j++) {
            int ia = tid + j * 256;
            int r = ia >> 4, c4 = ia & 15;
            CP16(dst + r * (F_ST * 4) + c4 * 16, kb + (size_t)r * DHn + c4 * 4);
        }
    };
    auto issueV = [&](int c, uint32_t bufoff) {
        const float* vb = vbase + (size_t)(c * 64) * DHn;
        uint32_t dst = sbase + bufoff * 4;
#pragma unroll
        for (int j = 0; j < 4; j++) {
            int ia = tid + j * 256;
            int r = ia >> 4, c4 = ia & 15;
            CP16(dst + r * (F_ST * 4) + c4 * 16, vb + (size_t)r * DHn + c4 * 4);
        }
    };

    // Q load + first K tile
    {
        uint32_t qdst = sbase + F_Q * 4;
#pragma unroll
        for (int j = 0; j < 8; j++) {
            int ia = tid + j * 256;
            int r = ia >> 4, c4 = ia & 15;
            CP16(qdst + r * (F_ST * 4) + c4 * 16, qb + (size_t)r * DHn + c4 * 4);
        }
        issueK(0, F_A);
        CP_COMMIT();
    }

    // zero-fill causal upper region (overlaps async loads)
    {
        int zc0 = (qt + 1) * 128;
        int nz4 = (Sn - zc0) >> 2;
        if (nz4 > 0) {
            const float4 z = make_float4(0.f, 0.f, 0.f, 0.f);
            for (int idx = tid; idx < 128 * nz4; idx += 256) {
                int r = idx / nz4, cc = idx - r * nz4;
                *(float4*)(attn_base + (size_t)r * Sn + zc0 + cc * 4) = z;
            }
        }
    }

    if (tid < 128) sm[F_L + tid] = 0.0f;

    const float* Qs = sm + F_Q;

    // ---------------- Phase 1: row sums of exp(S) ----------------
    float rs[8];
#pragma unroll
    for (int i = 0; i < 8; i++) rs[i] = 0.0f;

    for (int c = 0; c < ntiles; c++) {
        CP_WAIT0();
        __syncthreads();
        if (c + 1 < ntiles) {
            issueK(c + 1, ((c + 1) & 1) ? F_B : F_A);
            CP_COMMIT();
        }

        const float* K = sm + ((c & 1) ? F_B : F_A);
        float cs[4][2][4];
#pragma unroll
        for (int i = 0; i < 4; i++)
#pragma unroll
            for (int j = 0; j < 2; j++)
#pragma unroll
                for (int kk = 0; kk < 4; kk++) cs[i][j][kk] = 0.0f;

#pragma unroll
        for (int kk = 0; kk < 64; kk += 8) {
            uint32_t af[4][4], bf[2][2];
#pragma unroll
            for (int mt = 0; mt < 4; mt++) {
                int r0 = warpM * 64 + mt * 16 + g;
                af[mt][0] = tf32b(Qs[r0 * F_ST + kk + t]);
                af[mt][1] = tf32b(Qs[(r0 + 8) * F_ST + kk + t]);
                af[mt][2] = tf32b(Qs[r0 * F_ST + kk + t + 4]);
                af[mt][3] = tf32b(Qs[(r0 + 8) * F_ST + kk + t + 4]);
            }
#pragma unroll
            for (int nt = 0; nt < 2; nt++) {
                int n0 = warpN * 16 + nt * 8 + g;
                bf[nt][0] = tf32b(K[n0 * F_ST + kk + t]);
                bf[nt][1] = tf32b(K[n0 * F_ST + kk + t + 4]);
            }
#pragma unroll
            for (int mt = 0; mt < 4; mt++)
#pragma unroll
                for (int nt = 0; nt < 2; nt++)
                    mma_tf32(cs[mt][nt], af[mt], bf[nt]);
        }

#pragma unroll
        for (int mt = 0; mt < 4; mt++) {
#pragma unroll
            for (int half = 0; half < 2; half++) {
                int qi = qt * 128 + warpM * 64 + mt * 16 + g + half * 8;
                float acc = 0.0f;
#pragma unroll
                for (int nt = 0; nt < 2; nt++) {
                    int kj = c * 64 + warpN * 16 + nt * 8 + 2 * t;
                    float e0 = (kj <= qi) ? __expf(cs[mt][nt][half * 2] * SCALE_F) : 0.0f;
                    float e1 = (kj + 1 <= qi) ? __expf(cs[mt][nt][half * 2 + 1] * SCALE_F) : 0.0f;
                    acc += e0 + e1;
                }
                rs[mt * 2 + half] += acc;
            }
        }
    }

    // all warps done with bufs; prefetch phase-2 tiles, then reduce row sums
    __syncthreads();
    issueK(0, F_A); CP_COMMIT();
    issueV(0, F_B); CP_COMMIT();

#pragma unroll
    for (int i = 0; i < 8; i++) {
        rs[i] += __shfl_xor_sync(0xffffffffu, rs[i], 1);
        rs[i] += __shfl_xor_sync(0xffffffffu, rs[i], 2);
    }
    if (t == 0) {
#pragma unroll
        for (int i = 0; i < 8; i++) {
            int row = warpM * 64 + (i >> 1) * 16 + g + (i & 1) * 8;
            atomicAdd(&sm[F_L + row], rs[i]);
        }
    }
    __syncthreads();
    if (tid < 128) sm[F_INV + tid] = 1.0f / sm[F_L + tid];
    __syncthreads();

    // ---------------- Phase 2: P write + P@V ----------------
    float o[4][2][4];
#pragma unroll
    for (int i = 0; i < 4; i++)
#pragma unroll
        for (int j = 0; j < 2; j++)
#pragma unroll
            for (int kk = 0; kk < 4; kk++) o[i][j][kk] = 0.0f;

    float* Ps = sm + F_P;
    const float* invl = sm + F_INV;
    const float* Kb = sm + F_A;
    const float* Vb = sm + F_B;

    for (int c = 0; c < ntiles; c++) {
        // K(c) ready (V(c) is the newest pending group)
        CP_WAIT1();
        __syncthreads();

        float cs[4][2][4];
#pragma unroll
        for (int i = 0; i < 4; i++)
#pragma unroll
            for (int j = 0; j < 2; j++)
#pragma unroll
                for (int kk = 0; kk < 4; kk++) cs[i][j][kk] = 0.0f;

#pragma unroll
        for (int kk = 0; kk < 64; kk += 8) {
            uint32_t af[4][4], bf[2][2];
#pragma unroll
            for (int mt = 0; mt < 4; mt++) {
                int r0 = warpM * 64 + mt * 16 + g;
                af[mt][0] = tf32b(Qs[r0 * F_ST + kk + t]);
                af[mt][1] = tf32b(Qs[(r0 + 8) * F_ST + kk + t]);
                af[mt][2] = tf32b(Qs[r0 * F_ST + kk + t + 4]);
                af[mt][3] = tf32b(Qs[(r0 + 8) * F_ST + kk + t + 4]);
            }
#pragma unroll
            for (int nt = 0; nt < 2; nt++) {
                int n0 = warpN * 16 + nt * 8 + g;
                bf[nt][0] = tf32b(Kb[n0 * F_ST + kk + t]);
                bf[nt][1] = tf32b(Kb[n0 * F_ST + kk + t + 4]);
            }
#pragma unroll
            for (int mt = 0; mt < 4; mt++)
#pragma unroll
                for (int nt = 0; nt < 2; nt++)
                    mma_tf32(cs[mt][nt], af[mt], bf[nt]);
        }

        // all warps done reading K buf -> prefetch K(c+1) into A
        __syncthreads();
        if (c + 1 < ntiles) { issueK(c + 1, F_A); CP_COMMIT(); }

        // P = exp(S)*inv_l -> gmem attn + smem Ps  (overlaps K(c+1) load)
#pragma unroll
        for (int mt = 0; mt < 4; mt++) {
#pragma unroll
            for (int half = 0; half < 2; half++) {
                int rloc = warpM * 64 + mt * 16 + g + half * 8;
                int qi = qt * 128 + rloc;
                float inv = invl[rloc];
#pragma unroll
                for (int nt = 0; nt < 2; nt++) {
                    int klc = warpN * 16 + nt * 8 + 2 * t;
                    int kj = c * 64 + klc;
                    float p0 = (kj <= qi) ? __expf(cs[mt][nt][half * 2] * SCALE_F) * inv : 0.0f;
                    float p1 = (kj + 1 <= qi) ? __expf(cs[mt][nt][half * 2 + 1] * SCALE_F) * inv : 0.0f;
                    *(float2*)(attn_base + (size_t)rloc * Sn + kj) = make_float2(p0, p1);
                    Ps[rloc * F_ST + klc] = p0;
                    Ps[rloc * F_ST + klc + 1] = p1;
                }
            }
        }

        // V(c) ready
        if (c + 1 < ntiles) CP_WAIT1(); else CP_WAIT0();
        __syncthreads();   // Ps visible + V ready

        // O += P @ V
#pragma unroll
        for (int kk = 0; kk < 64; kk += 8) {
            uint32_t af[4][4], bf[2][2];
#pragma unroll
            for (int mt = 0; mt < 4; mt++) {
                int r0 = warpM * 64 + mt * 16 + g;
                af[mt][0] = tf32b(Ps[r0 * F_ST + kk + t]);
                af[mt][1] = tf32b(Ps[(r0 + 8) * F_ST + kk + t]);
                af[mt][2] = tf32b(Ps[r0 * F_ST + kk + t + 4]);
                af[mt][3] = tf32b(Ps[(r0 + 8) * F_ST + kk + t + 4]);
            }
#pragma unroll
            for (int nt = 0; nt < 2; nt++) {
                int n0 = warpN * 16 + nt * 8 + g;
                bf[nt][0] = tf32b(Vb[(kk + t) * F_ST + n0]);
                bf[nt][1] = tf32b(Vb[(kk + t + 4) * F_ST + n0]);
            }
#pragma unroll
            for (int mt = 0; mt < 4; mt++)
#pragma unroll
                for (int nt = 0; nt < 2; nt++)
                    mma_tf32(o[mt][nt], af[mt], bf[nt]);
        }

        // all warps done reading V buf -> prefetch V(c+1) into B
        __syncthreads();
        if (c + 1 < ntiles) { issueV(c + 1, F_B); CP_COMMIT(); }
    }

    // write O to ctx [B,S,H*DH]
#pragma unroll
    for (int mt = 0; mt < 4; mt++) {
#pragma unroll
        for (int nt = 0; nt < 2; nt++) {
            int s0 = qt * 128 + warpM * 64 + mt * 16 + g;
            int d0 = warpN * 16 + nt * 8 + 2 * t;
#pragma unroll
            for (int half = 0; half < 2; half++) {
                int s = s0 + half * 8;
                size_t base = ((size_t)b * Sn + s) * Dn + h * DHn + d0;
                ctx[base] = o[mt][nt][half * 2 + 0];
                ctx[base + 1] = o[mt][nt][half * 2 + 1];
            }
        }
    }
}

// ---------------------------------------------------------------------------
// Launch
// ---------------------------------------------------------------------------
extern "C" void kernel_launch(void* const* d_in, const int* in_sizes, int n_in,
                              void* d_out, int out_size)
{
    const float* Q  = (const float*)d_in[0];
    const float* K  = (const float*)d_in[1];
    const float* V  = (const float*)d_in[2];
    const float* wq = (const float*)d_in[4];
    const float* bq = (const float*)d_in[5];
    const float* wk = (const float*)d_in[6];
    const float* bk = (const float*)d_in[7];
    const float* wv = (const float*)d_in[8];
    const float* bv = (const float*)d_in[9];
    const float* wo = (const float*)d_in[10];
    const float* bo = (const float*)d_in[11];

    float* out = (float*)d_out;

    float* attn;
    if ((size_t)out_size >= OUT_ELEMS + ATTN_ELEMS) {
        attn = out + OUT_ELEMS;
    } else {
        void* p = nullptr;
        cudaGetSymbolAddress(&p, g_attn_scratch);
        attn = (float*)p;
    }

    float *gq, *gk, *gv, *gctx;
    {
        void* p;
        cudaGetSymbolAddress(&p, g_q);   gq   = (float*)p;
        cudaGetSymbolAddress(&p, g_k);   gk   = (float*)p;
        cudaGetSymbolAddress(&p, g_v);   gv   = (float*)p;
        cudaGetSymbolAddress(&p, g_ctx); gctx = (float*)p;
    }

    cudaFuncSetAttribute(tf32_gemm_kernel,
                         cudaFuncAttributeMaxDynamicSharedMemorySize, GEMM_SMEM);
    cudaFuncSetAttribute(fused_attn_kernel,
                         cudaFuncAttributeMaxDynamicSharedMemorySize, FUSED_SMEM);

    // QKV projections in one launch (grid.z selects which)
    dim3 gqkv(Dn / 128, Mn / 128, 3);   // (8, 64, 3)
    tf32_gemm_kernel<<<gqkv, 256, GEMM_SMEM>>>(
        Q, K, V, wq, wk, wv, bq, bk, bv, gq, gk, gv, 1);

    fused_attn_kernel<<<dim3(NQT, BHn), 256, FUSED_SMEM>>>(gq, gk, gv, attn, gctx);

    // output projection
    dim3 go(Dn / 128, Mn / 128, 1);
    tf32_gemm_kernel<<<go, 256, GEMM_SMEM>>>(
        gctx, gctx, gctx, wo, wo, wo, bo, bo, bo, out, out, out, 0);
}

// round 10
// speedup vs baseline: 1.0457x; 1.0457x over previous
#include <cuda_runtime.h>
#include <cstdint>
#include <math.h>

// Problem constants
#define Bn   4
#define Sn   2048
#define Dn   1024
#define Hn   16
#define DHn  64
#define BHn  (Bn * Hn)          // 64
#define Mn   (Bn * Sn)          // 8192
#define NQT  (Sn / 128)         // 16 q-tiles
#define SCALE_F 0.125f

#define OUT_ELEMS  ((size_t)Mn * Dn)            // 8,388,608
#define ATTN_ELEMS ((size_t)BHn * Sn * Sn)      // 268,435,456

// Scratch (device globals)
__device__ float g_q[Mn * Dn];            // [B,H,S,DH]
__device__ float g_k[Mn * Dn];
__device__ float g_v[Mn * Dn];
__device__ float g_ctx[Mn * Dn];          // [B,S,H*DH]
__device__ float g_attn_scratch[ATTN_ELEMS];

// ---------------------------------------------------------------------------
// PTX helpers
// ---------------------------------------------------------------------------
__device__ __forceinline__ uint32_t smem_u32(const void* p) {
    uint32_t a;
    asm("{ .reg .u64 t; cvta.to.shared.u64 t, %1; cvt.u32.u64 %0, t; }" : "=r"(a) : "l"(p));
    return a;
}
#define CP16(dst, src) \
    asm volatile("cp.async.cg.shared.global [%0], [%1], 16;" :: "r"(dst), "l"(src))
#define CP_COMMIT() asm volatile("cp.async.commit_group;")
#define CP_WAIT1()  asm volatile("cp.async.wait_group 1;")
#define CP_WAIT0()  asm volatile("cp.async.wait_group 0;")

__device__ __forceinline__ uint32_t tf32b(float f) {
    uint32_t r; asm("cvt.rna.tf32.f32 %0, %1;" : "=r"(r) : "f"(f));
    return r;
}
__device__ __forceinline__ void mma_tf32(float c[4], const uint32_t a[4], const uint32_t b[2]) {
    asm volatile(
        "mma.sync.aligned.m16n8k8.row.col.f32.tf32.tf32.f32 "
        "{%0,%1,%2,%3}, {%4,%5,%6,%7}, {%8,%9}, {%0,%1,%2,%3};"
        : "+f"(c[0]), "+f"(c[1]), "+f"(c[2]), "+f"(c[3])
        : "r"(a[0]), "r"(a[1]), "r"(a[2]), "r"(a[3]), "r"(b[0]), "r"(b[1]));
}

// ---------------------------------------------------------------------------
// tf32 mma GEMM, 2-stage pipeline, 2 CTAs/SM. QKV fused via blockIdx.z.
// ---------------------------------------------------------------------------
#define G_AST 36
#define G_BST 132
#define G_STAGE_F (128 * G_AST + 32 * G_BST)
#define GEMM_SMEM (2 * G_STAGE_F * 4)        // 70,656 bytes

__global__ __launch_bounds__(256, 2) void tf32_gemm_kernel(
    const float* __restrict__ X0, const float* __restrict__ X1, const float* __restrict__ X2,
    const float* __restrict__ W0, const float* __restrict__ W1, const float* __restrict__ W2,
    const float* __restrict__ B0, const float* __restrict__ B1, const float* __restrict__ B2,
    float* __restrict__ O0, float* __restrict__ O1, float* __restrict__ O2,
    int mode)
{
    extern __shared__ float sm[];
    const int z = blockIdx.z;
    const float* X    = (z == 0) ? X0 : (z == 1) ? X1 : X2;
    const float* W    = (z == 0) ? W0 : (z == 1) ? W1 : W2;
    const float* bias = (z == 0) ? B0 : (z == 1) ? B1 : B2;
    float* out        = (z == 0) ? O0 : (z == 1) ? O1 : O2;

    const int tid = threadIdx.x;
    const int wid = tid >> 5, lane = tid & 31;
    const int g = lane >> 2, t = lane & 3;
    const int warpM = wid & 1, warpN = wid >> 1;
    const int bm = blockIdx.y * 128, bn = blockIdx.x * 128;

    const uint32_t sbase = smem_u32(sm);

    float c[4][4][4];
#pragma unroll
    for (int i = 0; i < 4; i++)
#pragma unroll
        for (int j = 0; j < 4; j++)
#pragma unroll
            for (int k = 0; k < 4; k++) c[i][j][k] = 0.0f;

    auto issue = [&](int cidx, int buf) {
        const float* Xp = X + (size_t)bm * Dn + cidx * 32;
        const float* Wp = W + (size_t)(cidx * 32) * Dn + bn;
        uint32_t abase = sbase + buf * (G_STAGE_F * 4);
        uint32_t bbase = abase + 128 * G_AST * 4;
#pragma unroll
        for (int j = 0; j < 4; j++) {
            int ia = tid + j * 256;
            int ar = ia >> 3, ac = ia & 7;
            CP16(abase + ar * (G_AST * 4) + ac * 16, Xp + (size_t)ar * Dn + ac * 4);
            int br = ia >> 5, bc = ia & 31;
            CP16(bbase + br * (G_BST * 4) + bc * 16, Wp + (size_t)br * Dn + bc * 4);
        }
    };

    issue(0, 0); CP_COMMIT();

    const int NCH = Dn / 32;   // 32
    for (int s = 0; s < NCH; s++) {
        CP_WAIT0();
        __syncthreads();
        if (s + 1 < NCH) { issue(s + 1, (s + 1) & 1); CP_COMMIT(); }

        const float* A = sm + (s & 1) * G_STAGE_F;
        const float* B = A + 128 * G_AST;
#pragma unroll
        for (int kk = 0; kk < 32; kk += 8) {
            uint32_t af[4][4], bf[4][2];
#pragma unroll
            for (int mt = 0; mt < 4; mt++) {
                int r0 = warpM * 64 + mt * 16 + g;
                af[mt][0] = tf32b(A[r0 * G_AST + kk + t]);
                af[mt][1] = tf32b(A[(r0 + 8) * G_AST + kk + t]);
                af[mt][2] = tf32b(A[r0 * G_AST + kk + t + 4]);
                af[mt][3] = tf32b(A[(r0 + 8) * G_AST + kk + t + 4]);
            }
#pragma unroll
            for (int nt = 0; nt < 4; nt++) {
                int n0 = warpN * 32 + nt * 8 + g;
                bf[nt][0] = tf32b(B[(kk + t) * G_BST + n0]);
                bf[nt][1] = tf32b(B[(kk + t + 4) * G_BST + n0]);
            }
#pragma unroll
            for (int mt = 0; mt < 4; mt++)
#pragma unroll
                for (int nt = 0; nt < 4; nt++)
                    mma_tf32(c[mt][nt], af[mt], bf[nt]);
        }
    }

#pragma unroll
    for (int mt = 0; mt < 4; mt++) {
#pragma unroll
        for (int nt = 0; nt < 4; nt++) {
            int m0 = bm + warpM * 64 + mt * 16 + g;
            int n0 = bn + warpN * 32 + nt * 8 + 2 * t;
#pragma unroll
            for (int half = 0; half < 2; half++) {
                int m = m0 + half * 8;
                float v0 = c[mt][nt][half * 2 + 0] + bias[n0];
                float v1 = c[mt][nt][half * 2 + 1] + bias[n0 + 1];
                if (mode == 0) {
                    out[(size_t)m * Dn + n0] = v0;
                    out[(size_t)m * Dn + n0 + 1] = v1;
                } else {
                    int b = m >> 11, sq = m & (Sn - 1);
                    int h = n0 >> 6, d = n0 & 63;
                    size_t base = (((size_t)b * Hn + h) * Sn + sq) * DHn + d;
                    out[base] = v0;
                    out[base + 1] = v1;
                }
            }
        }
    }
}

// ---------------------------------------------------------------------------
// Fused attention, 2 CTAs/SM (105.5 KB smem).
// Phase 1: row sums of exp(QK^T), K ping-pong in bufs A/B.
// Phase 2: K in A, V in B; attn written from smem Ps as coalesced float4.
// Causal mask applied at tile granularity (only c >= 2*qt needs per-element).
// ---------------------------------------------------------------------------
#define F_ST   68
#define F_Q    0                          // 128 x 68
#define F_A    (128 * F_ST)               // 64 x 68
#define F_B    (F_A + 64 * F_ST)          // 64 x 68
#define F_P    (F_B + 64 * F_ST)          // 128 x 68
#define F_L    (F_P + 128 * F_ST)         // 128
#define F_INV  (F_L + 128)                // 128
#define FUSED_SMEM ((F_INV + 128) * 4)    // 105,472 bytes

__global__ __launch_bounds__(256, 2) void fused_attn_kernel(
    const float* __restrict__ q, const float* __restrict__ k,
    const float* __restrict__ v, float* __restrict__ attn,
    float* __restrict__ ctx)
{
    extern __shared__ float sm[];
    const int bh = blockIdx.y;
    const int qt = (NQT - 1) - blockIdx.x;   // heavy tiles first
    const int b = bh >> 4, h = bh & 15;

    const int tid = threadIdx.x;
    const int wid = tid >> 5, lane = tid & 31;
    const int g = lane >> 2, t = lane & 3;
    const int warpM = wid & 1, warpN = wid >> 1;   // 2 x 4

    const uint32_t sbase = smem_u32(sm);
    const float* qb = q + ((size_t)bh * Sn + qt * 128) * DHn;
    const float* kbase = k + (size_t)bh * Sn * DHn;
    const float* vbase = v + (size_t)bh * Sn * DHn;
    float* attn_base = attn + ((size_t)bh * Sn + qt * 128) * Sn;

    const int ntiles = 2 * (qt + 1);   // 64-row K/V tiles

    auto issueK = [&](int c, uint32_t bufoff) {
        const float* kb = kbase + (size_t)(c * 64) * DHn;
        uint32_t dst = sbase + bufoff * 4;
#pragma unroll
        for (int j = 0; j < 4; j++) {
            int ia = tid + j * 256;
            int r = ia >> 4, c4 = ia & 15;
            CP16(dst + r * (F_ST * 4) + c4 * 16, kb + (size_t)r * DHn + c4 * 4);
        }
    };
    auto issueV = [&](int c, uint32_t bufoff) {
        const float* vb = vbase + (size_t)(c * 64) * DHn;
        uint32_t dst = sbase + bufoff * 4;
#pragma unroll
        for (int j = 0; j < 4; j++) {
            int ia = tid + j * 256;
            int r = ia >> 4, c4 = ia & 15;
            CP16(dst + r * (F_ST * 4) + c4 * 16, vb + (size_t)r * DHn + c4 * 4);
        }
    };

    // Q load + first K tile
    {
        uint32_t qdst = sbase + F_Q * 4;
#pragma unroll
        for (int j = 0; j < 8; j++) {
            int ia = tid + j * 256;
            int r = ia >> 4, c4 = ia & 15;
            CP16(qdst + r * (F_ST * 4) + c4 * 16, qb + (size_t)r * DHn + c4 * 4);
        }
        issueK(0, F_A);
        CP_COMMIT();
    }

    // zero-fill causal upper region (overlaps async loads)
    {
        int zc0 = (qt + 1) * 128;
        int nz4 = (Sn - zc0) >> 2;
        if (nz4 > 0) {
            const float4 z = make_float4(0.f, 0.f, 0.f, 0.f);
            for (int idx = tid; idx < 128 * nz4; idx += 256) {
                int r = idx / nz4, cc = idx - r * nz4;
                *(float4*)(attn_base + (size_t)r * Sn + zc0 + cc * 4) = z;
            }
        }
    }

    if (tid < 128) sm[F_L + tid] = 0.0f;

    const float* Qs = sm + F_Q;

    // ---------------- Phase 1: row sums of exp(S) ----------------
    float rs[8];
#pragma unroll
    for (int i = 0; i < 8; i++) rs[i] = 0.0f;

    for (int c = 0; c < ntiles; c++) {
        CP_WAIT0();
        __syncthreads();
        if (c + 1 < ntiles) {
            issueK(c + 1, ((c + 1) & 1) ? F_B : F_A);
            CP_COMMIT();
        }

        const float* K = sm + ((c & 1) ? F_B : F_A);
        float cs[4][2][4];
#pragma unroll
        for (int i = 0; i < 4; i++)
#pragma unroll
            for (int j = 0; j < 2; j++)
#pragma unroll
                for (int kk = 0; kk < 4; kk++) cs[i][j][kk] = 0.0f;

#pragma unroll
        for (int kk = 0; kk < 64; kk += 8) {
            uint32_t af[4][4], bf[2][2];
#pragma unroll
            for (int mt = 0; mt < 4; mt++) {
                int r0 = warpM * 64 + mt * 16 + g;
                af[mt][0] = tf32b(Qs[r0 * F_ST + kk + t]);
                af[mt][1] = tf32b(Qs[(r0 + 8) * F_ST + kk + t]);
                af[mt][2] = tf32b(Qs[r0 * F_ST + kk + t + 4]);
                af[mt][3] = tf32b(Qs[(r0 + 8) * F_ST + kk + t + 4]);
            }
#pragma unroll
            for (int nt = 0; nt < 2; nt++) {
                int n0 = warpN * 16 + nt * 8 + g;
                bf[nt][0] = tf32b(K[n0 * F_ST + kk + t]);
                bf[nt][1] = tf32b(K[n0 * F_ST + kk + t + 4]);
            }
#pragma unroll
            for (int mt = 0; mt < 4; mt++)
#pragma unroll
                for (int nt = 0; nt < 2; nt++)
                    mma_tf32(cs[mt][nt], af[mt], bf[nt]);
        }

        if (c < 2 * qt) {
            // fully unmasked tile: no per-element predicates
#pragma unroll
            for (int mt = 0; mt < 4; mt++)
#pragma unroll
                for (int half = 0; half < 2; half++) {
                    float acc = 0.0f;
#pragma unroll
                    for (int nt = 0; nt < 2; nt++) {
                        acc += __expf(cs[mt][nt][half * 2] * SCALE_F);
                        acc += __expf(cs[mt][nt][half * 2 + 1] * SCALE_F);
                    }
                    rs[mt * 2 + half] += acc;
                }
        } else {
#pragma unroll
            for (int mt = 0; mt < 4; mt++)
#pragma unroll
                for (int half = 0; half < 2; half++) {
                    int qi = qt * 128 + warpM * 64 + mt * 16 + g + half * 8;
                    float acc = 0.0f;
#pragma unroll
                    for (int nt = 0; nt < 2; nt++) {
                        int kj = c * 64 + warpN * 16 + nt * 8 + 2 * t;
                        if (kj <= qi)     acc += __expf(cs[mt][nt][half * 2] * SCALE_F);
                        if (kj + 1 <= qi) acc += __expf(cs[mt][nt][half * 2 + 1] * SCALE_F);
                    }
                    rs[mt * 2 + half] += acc;
                }
        }
    }

    // all warps done with bufs; prefetch phase-2 tiles, then reduce row sums
    __syncthreads();
    issueK(0, F_A); CP_COMMIT();
    issueV(0, F_B); CP_COMMIT();

#pragma unroll
    for (int i = 0; i < 8; i++) {
        rs[i] += __shfl_xor_sync(0xffffffffu, rs[i], 1);
        rs[i] += __shfl_xor_sync(0xffffffffu, rs[i], 2);
    }
    if (t == 0) {
#pragma unroll
        for (int i = 0; i < 8; i++) {
            int row = warpM * 64 + (i >> 1) * 16 + g + (i & 1) * 8;
            atomicAdd(&sm[F_L + row], rs[i]);
        }
    }
    __syncthreads();
    if (tid < 128) sm[F_INV + tid] = 1.0f / sm[F_L + tid];
    __syncthreads();

    // ---------------- Phase 2: attn write (coalesced) + P@V ----------------
    float o[4][2][4];
#pragma unroll
    for (int i = 0; i < 4; i++)
#pragma unroll
        for (int j = 0; j < 2; j++)
#pragma unroll
            for (int kk = 0; kk < 4; kk++) o[i][j][kk] = 0.0f;

    float* Ps = sm + F_P;
    const float* invl = sm + F_INV;
    const float* Kb = sm + F_A;
    const float* Vb = sm + F_B;

    // store mapping: 128 rows x 16 float4 columns, 8 rows per thread
    const int st_r0 = tid >> 4, st_c = (tid & 15) * 4;

    for (int c = 0; c < ntiles; c++) {
        // K(c) ready (V(c) is the newest pending group)
        CP_WAIT1();
        __syncthreads();

        float cs[4][2][4];
#pragma unroll
        for (int i = 0; i < 4; i++)
#pragma unroll
            for (int j = 0; j < 2; j++)
#pragma unroll
                for (int kk = 0; kk < 4; kk++) cs[i][j][kk] = 0.0f;

#pragma unroll
        for (int kk = 0; kk < 64; kk += 8) {
            uint32_t af[4][4], bf[2][2];
#pragma unroll
            for (int mt = 0; mt < 4; mt++) {
                int r0 = warpM * 64 + mt * 16 + g;
                af[mt][0] = tf32b(Qs[r0 * F_ST + kk + t]);
                af[mt][1] = tf32b(Qs[(r0 + 8) * F_ST + kk + t]);
                af[mt][2] = tf32b(Qs[r0 * F_ST + kk + t + 4]);
                af[mt][3] = tf32b(Qs[(r0 + 8) * F_ST + kk + t + 4]);
            }
#pragma unroll
            for (int nt = 0; nt < 2; nt++) {
                int n0 = warpN * 16 + nt * 8 + g;
                bf[nt][0] = tf32b(Kb[n0 * F_ST + kk + t]);
                bf[nt][1] = tf32b(Kb[n0 * F_ST + kk + t + 4]);
            }
#pragma unroll
            for (int mt = 0; mt < 4; mt++)
#pragma unroll
                for (int nt = 0; nt < 2; nt++)
                    mma_tf32(cs[mt][nt], af[mt], bf[nt]);
        }

        // all warps done reading K buf -> prefetch K(c+1) into A
        __syncthreads();
        if (c + 1 < ntiles) { issueK(c + 1, F_A); CP_COMMIT(); }

        // P = exp(S)*inv_l -> smem Ps  (overlaps K(c+1) load)
        if (c < 2 * qt) {
#pragma unroll
            for (int mt = 0; mt < 4; mt++)
#pragma unroll
                for (int half = 0; half < 2; half++) {
                    int rloc = warpM * 64 + mt * 16 + g + half * 8;
                    float inv = invl[rloc];
#pragma unroll
                    for (int nt = 0; nt < 2; nt++) {
                        int klc = warpN * 16 + nt * 8 + 2 * t;
                        float p0 = __expf(cs[mt][nt][half * 2] * SCALE_F) * inv;
                        float p1 = __expf(cs[mt][nt][half * 2 + 1] * SCALE_F) * inv;
                        *(float2*)&Ps[rloc * F_ST + klc] = make_float2(p0, p1);
                    }
                }
        } else {
#pragma unroll
            for (int mt = 0; mt < 4; mt++)
#pragma unroll
                for (int half = 0; half < 2; half++) {
                    int rloc = warpM * 64 + mt * 16 + g + half * 8;
                    int qi = qt * 128 + rloc;
                    float inv = invl[rloc];
#pragma unroll
                    for (int nt = 0; nt < 2; nt++) {
                        int klc = warpN * 16 + nt * 8 + 2 * t;
                        int kj = c * 64 + klc;
                        float p0 = (kj <= qi) ? __expf(cs[mt][nt][half * 2] * SCALE_F) * inv : 0.0f;
                        float p1 = (kj + 1 <= qi) ? __expf(cs[mt][nt][half * 2 + 1] * SCALE_F) * inv : 0.0f;
                        *(float2*)&Ps[rloc * F_ST + klc] = make_float2(p0, p1);
                    }
                }
        }

        // V(c) ready
        if (c + 1 < ntiles) CP_WAIT1(); else CP_WAIT0();
        __syncthreads();   // Ps visible + V ready

        // coalesced attn store from Ps (fire-and-forget, overlaps PV mma issue)
        {
            float* dst = attn_base + c * 64 + st_c;
#pragma unroll
            for (int j = 0; j < 8; j++) {
                int r = st_r0 + j * 16;
                *(float4*)(dst + (size_t)r * Sn) = *(const float4*)&Ps[r * F_ST + st_c];
            }
        }

        // O += P @ V
#pragma unroll
        for (int kk = 0; kk < 64; kk += 8) {
            uint32_t af[4][4], bf[2][2];
#pragma unroll
            for (int mt = 0; mt < 4; mt++) {
                int r0 = warpM * 64 + mt * 16 + g;
                af[mt][0] = tf32b(Ps[r0 * F_ST + kk + t]);
                af[mt][1] = tf32b(Ps[(r0 + 8) * F_ST + kk + t]);
                af[mt][2] = tf32b(Ps[r0 * F_ST + kk + t + 4]);
                af[mt][3] = tf32b(Ps[(r0 + 8) * F_ST + kk + t + 4]);
            }
#pragma unroll
            for (int nt = 0; nt < 2; nt++) {
                int n0 = warpN * 16 + nt * 8 + g;
                bf[nt][0] = tf32b(Vb[(kk + t) * F_ST + n0]);
                bf[nt][1] = tf32b(Vb[(kk + t + 4) * F_ST + n0]);
            }
#pragma unroll
            for (int mt = 0; mt < 4; mt++)
#pragma unroll
                for (int nt = 0; nt < 2; nt++)
                    mma_tf32(o[mt][nt], af[mt], bf[nt]);
        }

        // all warps done reading V buf -> prefetch V(c+1) into B
        __syncthreads();
        if (c + 1 < ntiles) { issueV(c + 1, F_B); CP_COMMIT(); }
    }

    // write O to ctx [B,S,H*DH]
#pragma unroll
    for (int mt = 0; mt < 4; mt++) {
#pragma unroll
        for (int nt = 0; nt < 2; nt++) {
            int s0 = qt * 128 + warpM * 64 + mt * 16 + g;
            int d0 = warpN * 16 + nt * 8 + 2 * t;
#pragma unroll
            for (int half = 0; half < 2; half++) {
                int s = s0 + half * 8;
                size_t base = ((size_t)b * Sn + s) * Dn + h * DHn + d0;
                ctx[base] = o[mt][nt][half * 2 + 0];
                ctx[base + 1] = o[mt][nt][half * 2 + 1];
            }
        }
    }
}

// ---------------------------------------------------------------------------
// Launch
// ---------------------------------------------------------------------------
extern "C" void kernel_launch(void* const* d_in, const int* in_sizes, int n_in,
                              void* d_out, int out_size)
{
    const float* Q  = (const float*)d_in[0];
    const float* K  = (const float*)d_in[1];
    const float* V  = (const float*)d_in[2];
    const float* wq = (const float*)d_in[4];
    const float* bq = (const float*)d_in[5];
    const float* wk = (const float*)d_in[6];
    const float* bk = (const float*)d_in[7];
    const float* wv = (const float*)d_in[8];
    const float* bv = (const float*)d_in[9];
    const float* wo = (const float*)d_in[10];
    const float* bo = (const float*)d_in[11];

    float* out = (float*)d_out;

    float* attn;
    if ((size_t)out_size >= OUT_ELEMS + ATTN_ELEMS) {
        attn = out + OUT_ELEMS;
    } else {
        void* p = nullptr;
        cudaGetSymbolAddress(&p, g_attn_scratch);
        attn = (float*)p;
    }

    float *gq, *gk, *gv, *gctx;
    {
        void* p;
        cudaGetSymbolAddress(&p, g_q);   gq   = (float*)p;
        cudaGetSymbolAddress(&p, g_k);   gk   = (float*)p;
        cudaGetSymbolAddress(&p, g_v);   gv   = (float*)p;
        cudaGetSymbolAddress(&p, g_ctx); gctx = (float*)p;
    }

    cudaFuncSetAttribute(tf32_gemm_kernel,
                         cudaFuncAttributeMaxDynamicSharedMemorySize, GEMM_SMEM);
    cudaFuncSetAttribute(fused_attn_kernel,
                         cudaFuncAttributeMaxDynamicSharedMemorySize, FUSED_SMEM);

    // QKV projections in one launch (grid.z selects which)
    dim3 gqkv(Dn / 128, Mn / 128, 3);   // (8, 64, 3)
    tf32_gemm_kernel<<<gqkv, 256, GEMM_SMEM>>>(
        Q, K, V, wq, wk, wv, bq, bk, bv, gq, gk, gv, 1);

    fused_attn_kernel<<<dim3(NQT, BHn), 256, FUSED_SMEM>>>(gq, gk, gv, attn, gctx);

    // output projection
    dim3 go(Dn / 128, Mn / 128, 1);
    tf32_gemm_kernel<<<go, 256, GEMM_SMEM>>>(
        gctx, gctx, gctx, wo, wo, wo, bo, bo, bo, out, out, out, 0);
}

// round 11
// speedup vs baseline: 1.0495x; 1.0036x over previous
#include <cuda_runtime.h>
#include <cstdint>
#include <math.h>

// Problem constants
#define Bn   4
#define Sn   2048
#define Dn   1024
#define Hn   16
#define DHn  64
#define BHn  (Bn * Hn)          // 64
#define Mn   (Bn * Sn)          // 8192
#define NQT  (Sn / 128)         // 16 q-tiles
#define SCALE_F 0.125f

#define OUT_ELEMS  ((size_t)Mn * Dn)            // 8,388,608
#define ATTN_ELEMS ((size_t)BHn * Sn * Sn)      // 268,435,456

// Scratch (device globals)
__device__ float g_q[Mn * Dn];            // [B,H,S,DH]
__device__ float g_k[Mn * Dn];
__device__ float g_v[Mn * Dn];
__device__ float g_ctx[Mn * Dn];          // [B,S,H*DH]
__device__ float g_attn_scratch[ATTN_ELEMS];

// ---------------------------------------------------------------------------
// PTX helpers
// ---------------------------------------------------------------------------
__device__ __forceinline__ uint32_t smem_u32(const void* p) {
    uint32_t a;
    asm("{ .reg .u64 t; cvta.to.shared.u64 t, %1; cvt.u32.u64 %0, t; }" : "=r"(a) : "l"(p));
    return a;
}
#define CP16(dst, src) \
    asm volatile("cp.async.cg.shared.global [%0], [%1], 16;" :: "r"(dst), "l"(src))
#define CP_COMMIT() asm volatile("cp.async.commit_group;")
#define CP_WAIT1()  asm volatile("cp.async.wait_group 1;")
#define CP_WAIT0()  asm volatile("cp.async.wait_group 0;")

__device__ __forceinline__ uint32_t tf32b(float f) {
    uint32_t r; asm("cvt.rna.tf32.f32 %0, %1;" : "=r"(r) : "f"(f));
    return r;
}
__device__ __forceinline__ void mma_tf32(float c[4], const uint32_t a[4], const uint32_t b[2]) {
    asm volatile(
        "mma.sync.aligned.m16n8k8.row.col.f32.tf32.tf32.f32 "
        "{%0,%1,%2,%3}, {%4,%5,%6,%7}, {%8,%9}, {%0,%1,%2,%3};"
        : "+f"(c[0]), "+f"(c[1]), "+f"(c[2]), "+f"(c[3])
        : "r"(a[0]), "r"(a[1]), "r"(a[2]), "r"(a[3]), "r"(b[0]), "r"(b[1]));
}

// ---------------------------------------------------------------------------
// tf32 mma GEMM, 2-stage pipeline, 2 CTAs/SM. QKV fused via blockIdx.z.
// ---------------------------------------------------------------------------
#define G_AST 36
#define G_BST 132
#define G_STAGE_F (128 * G_AST + 32 * G_BST)
#define GEMM_SMEM (2 * G_STAGE_F * 4)        // 70,656 bytes

__global__ __launch_bounds__(256, 2) void tf32_gemm_kernel(
    const float* __restrict__ X0, const float* __restrict__ X1, const float* __restrict__ X2,
    const float* __restrict__ W0, const float* __restrict__ W1, const float* __restrict__ W2,
    const float* __restrict__ B0, const float* __restrict__ B1, const float* __restrict__ B2,
    float* __restrict__ O0, float* __restrict__ O1, float* __restrict__ O2,
    int mode)
{
    extern __shared__ float sm[];
    const int z = blockIdx.z;
    const float* X    = (z == 0) ? X0 : (z == 1) ? X1 : X2;
    const float* W    = (z == 0) ? W0 : (z == 1) ? W1 : W2;
    const float* bias = (z == 0) ? B0 : (z == 1) ? B1 : B2;
    float* out        = (z == 0) ? O0 : (z == 1) ? O1 : O2;

    const int tid = threadIdx.x;
    const int wid = tid >> 5, lane = tid & 31;
    const int g = lane >> 2, t = lane & 3;
    const int warpM = wid & 1, warpN = wid >> 1;
    const int bm = blockIdx.y * 128, bn = blockIdx.x * 128;

    const uint32_t sbase = smem_u32(sm);

    float c[4][4][4];
#pragma unroll
    for (int i = 0; i < 4; i++)
#pragma unroll
        for (int j = 0; j < 4; j++)
#pragma unroll
            for (int k = 0; k < 4; k++) c[i][j][k] = 0.0f;

    auto issue = [&](int cidx, int buf) {
        const float* Xp = X + (size_t)bm * Dn + cidx * 32;
        const float* Wp = W + (size_t)(cidx * 32) * Dn + bn;
        uint32_t abase = sbase + buf * (G_STAGE_F * 4);
        uint32_t bbase = abase + 128 * G_AST * 4;
#pragma unroll
        for (int j = 0; j < 4; j++) {
            int ia = tid + j * 256;
            int ar = ia >> 3, ac = ia & 7;
            CP16(abase + ar * (G_AST * 4) + ac * 16, Xp + (size_t)ar * Dn + ac * 4);
            int br = ia >> 5, bc = ia & 31;
            CP16(bbase + br * (G_BST * 4) + bc * 16, Wp + (size_t)br * Dn + bc * 4);
        }
    };

    issue(0, 0); CP_COMMIT();

    const int NCH = Dn / 32;   // 32
    for (int s = 0; s < NCH; s++) {
        CP_WAIT0();
        __syncthreads();
        if (s + 1 < NCH) { issue(s + 1, (s + 1) & 1); CP_COMMIT(); }

        const float* A = sm + (s & 1) * G_STAGE_F;
        const float* B = A + 128 * G_AST;
#pragma unroll
        for (int kk = 0; kk < 32; kk += 8) {
            uint32_t af[4][4], bf[4][2];
#pragma unroll
            for (int mt = 0; mt < 4; mt++) {
                int r0 = warpM * 64 + mt * 16 + g;
                af[mt][0] = tf32b(A[r0 * G_AST + kk + t]);
                af[mt][1] = tf32b(A[(r0 + 8) * G_AST + kk + t]);
                af[mt][2] = tf32b(A[r0 * G_AST + kk + t + 4]);
                af[mt][3] = tf32b(A[(r0 + 8) * G_AST + kk + t + 4]);
            }
#pragma unroll
            for (int nt = 0; nt < 4; nt++) {
                int n0 = warpN * 32 + nt * 8 + g;
                bf[nt][0] = tf32b(B[(kk + t) * G_BST + n0]);
                bf[nt][1] = tf32b(B[(kk + t + 4) * G_BST + n0]);
            }
#pragma unroll
            for (int mt = 0; mt < 4; mt++)
#pragma unroll
                for (int nt = 0; nt < 4; nt++)
                    mma_tf32(c[mt][nt], af[mt], bf[nt]);
        }
    }

#pragma unroll
    for (int mt = 0; mt < 4; mt++) {
#pragma unroll
        for (int nt = 0; nt < 4; nt++) {
            int m0 = bm + warpM * 64 + mt * 16 + g;
            int n0 = bn + warpN * 32 + nt * 8 + 2 * t;
#pragma unroll
            for (int half = 0; half < 2; half++) {
                int m = m0 + half * 8;
                float v0 = c[mt][nt][half * 2 + 0] + bias[n0];
                float v1 = c[mt][nt][half * 2 + 1] + bias[n0 + 1];
                if (mode == 0) {
                    out[(size_t)m * Dn + n0] = v0;
                    out[(size_t)m * Dn + n0 + 1] = v1;
                } else {
                    int b = m >> 11, sq = m & (Sn - 1);
                    int h = n0 >> 6, d = n0 & 63;
                    size_t base = (((size_t)b * Hn + h) * Sn + sq) * DHn + d;
                    out[base] = v0;
                    out[base + 1] = v1;
                }
            }
        }
    }
}

// ---------------------------------------------------------------------------
// Fused attention, 2 CTAs/SM (105.5 KB smem).
// Phase 1: row sums of exp(QK^T), K ping-pong in bufs A/B.
// Phase 2: K in A, V in B; attn written from smem Ps as coalesced float4.
// Causal mask applied at tile granularity (only c >= 2*qt needs per-element).
// ---------------------------------------------------------------------------
#define F_ST   68
#define F_Q    0                          // 128 x 68
#define F_A    (128 * F_ST)               // 64 x 68
#define F_B    (F_A + 64 * F_ST)          // 64 x 68
#define F_P    (F_B + 64 * F_ST)          // 128 x 68
#define F_L    (F_P + 128 * F_ST)         // 128
#define F_INV  (F_L + 128)                // 128
#define FUSED_SMEM ((F_INV + 128) * 4)    // 105,472 bytes

__global__ __launch_bounds__(256, 2) void fused_attn_kernel(
    const float* __restrict__ q, const float* __restrict__ k,
    const float* __restrict__ v, float* __restrict__ attn,
    float* __restrict__ ctx)
{
    extern __shared__ float sm[];
    const int bh = blockIdx.y;
    const int qt = (NQT - 1) - blockIdx.x;   // heavy tiles first
    const int b = bh >> 4, h = bh & 15;

    const int tid = threadIdx.x;
    const int wid = tid >> 5, lane = tid & 31;
    const int g = lane >> 2, t = lane & 3;
    const int warpM = wid & 1, warpN = wid >> 1;   // 2 x 4

    const uint32_t sbase = smem_u32(sm);
    const float* qb = q + ((size_t)bh * Sn + qt * 128) * DHn;
    const float* kbase = k + (size_t)bh * Sn * DHn;
    const float* vbase = v + (size_t)bh * Sn * DHn;
    float* attn_base = attn + ((size_t)bh * Sn + qt * 128) * Sn;

    const int ntiles = 2 * (qt + 1);   // 64-row K/V tiles

    auto issueK = [&](int c, uint32_t bufoff) {
        const float* kb = kbase + (size_t)(c * 64) * DHn;
        uint32_t dst = sbase + bufoff * 4;
#pragma unroll
        for (int j = 0; j < 4; j++) {
            int ia = tid + j * 256;
            int r = ia >> 4, c4 = ia & 15;
            CP16(dst + r * (F_ST * 4) + c4 * 16, kb + (size_t)r * DHn + c4 * 4);
        }
    };
    auto issueV = [&](int c, uint32_t bufoff) {
        const float* vb = vbase + (size_t)(c * 64) * DHn;
        uint32_t dst = sbase + bufoff * 4;
#pragma unroll
        for (int j = 0; j < 4; j++) {
            int ia = tid + j * 256;
            int r = ia >> 4, c4 = ia & 15;
            CP16(dst + r * (F_ST * 4) + c4 * 16, vb + (size_t)r * DHn + c4 * 4);
        }
    };

    // Q load + first K tile
    {
        uint32_t qdst = sbase + F_Q * 4;
#pragma unroll
        for (int j = 0; j < 8; j++) {
            int ia = tid + j * 256;
            int r = ia >> 4, c4 = ia & 15;
            CP16(qdst + r * (F_ST * 4) + c4 * 16, qb + (size_t)r * DHn + c4 * 4);
        }
        issueK(0, F_A);
        CP_COMMIT();
    }

    // zero-fill causal upper region (overlaps async loads)
    {
        int zc0 = (qt + 1) * 128;
        int nz4 = (Sn - zc0) >> 2;
        if (nz4 > 0) {
            const float4 z = make_float4(0.f, 0.f, 0.f, 0.f);
            for (int idx = tid; idx < 128 * nz4; idx += 256) {
                int r = idx / nz4, cc = idx - r * nz4;
                *(float4*)(attn_base + (size_t)r * Sn + zc0 + cc * 4) = z;
            }
        }
    }

    if (tid < 128) sm[F_L + tid] = 0.0f;

    const float* Qs = sm + F_Q;

    // ---------------- Phase 1: row sums of exp(S) ----------------
    float rs[8];
#pragma unroll
    for (int i = 0; i < 8; i++) rs[i] = 0.0f;

    for (int c = 0; c < ntiles; c++) {
        CP_WAIT0();
        __syncthreads();
        if (c + 1 < ntiles) {
            issueK(c + 1, ((c + 1) & 1) ? F_B : F_A);
            CP_COMMIT();
        }

        const float* K = sm + ((c & 1) ? F_B : F_A);
        float cs[4][2][4];
#pragma unroll
        for (int i = 0; i < 4; i++)
#pragma unroll
            for (int j = 0; j < 2; j++)
#pragma unroll
                for (int kk = 0; kk < 4; kk++) cs[i][j][kk] = 0.0f;

#pragma unroll
        for (int kk = 0; kk < 64; kk += 8) {
            uint32_t af[4][4], bf[2][2];
#pragma unroll
            for (int mt = 0; mt < 4; mt++) {
                int r0 = warpM * 64 + mt * 16 + g;
                af[mt][0] = tf32b(Qs[r0 * F_ST + kk + t]);
                af[mt][1] = tf32b(Qs[(r0 + 8) * F_ST + kk + t]);
                af[mt][2] = tf32b(Qs[r0 * F_ST + kk + t + 4]);
                af[mt][3] = tf32b(Qs[(r0 + 8) * F_ST + kk + t + 4]);
            }
#pragma unroll
            for (int nt = 0; nt < 2; nt++) {
                int n0 = warpN * 16 + nt * 8 + g;
                bf[nt][0] = tf32b(K[n0 * F_ST + kk + t]);
                bf[nt][1] = tf32b(K[n0 * F_ST + kk + t + 4]);
            }
#pragma unroll
            for (int mt = 0; mt < 4; mt++)
#pragma unroll
                for (int nt = 0; nt < 2; nt++)
                    mma_tf32(cs[mt][nt], af[mt], bf[nt]);
        }

        if (c < 2 * qt) {
            // fully unmasked tile: no per-element predicates
#pragma unroll
            for (int mt = 0; mt < 4; mt++)
#pragma unroll
                for (int half = 0; half < 2; half++) {
                    float acc = 0.0f;
#pragma unroll
                    for (int nt = 0; nt < 2; nt++) {
                        acc += __expf(cs[mt][nt][half * 2] * SCALE_F);
                        acc += __expf(cs[mt][nt][half * 2 + 1] * SCALE_F);
                    }
                    rs[mt * 2 + half] += acc;
                }
        } else {
#pragma unroll
            for (int mt = 0; mt < 4; mt++)
#pragma unroll
                for (int half = 0; half < 2; half++) {
                    int qi = qt * 128 + warpM * 64 + mt * 16 + g + half * 8;
                    float acc = 0.0f;
#pragma unroll
                    for (int nt = 0; nt < 2; nt++) {
                        int kj = c * 64 + warpN * 16 + nt * 8 + 2 * t;
                        if (kj <= qi)     acc += __expf(cs[mt][nt][half * 2] * SCALE_F);
                        if (kj + 1 <= qi) acc += __expf(cs[mt][nt][half * 2 + 1] * SCALE_F);
                    }
                    rs[mt * 2 + half] += acc;
                }
        }
    }

    // all warps done with bufs; prefetch phase-2 tiles, then reduce row sums
    __syncthreads();
    issueK(0, F_A); CP_COMMIT();
    issueV(0, F_B); CP_COMMIT();

#pragma unroll
    for (int i = 0; i < 8; i++) {
        rs[i] += __shfl_xor_sync(0xffffffffu, rs[i], 1);
        rs[i] += __shfl_xor_sync(0xffffffffu, rs[i], 2);
    }
    if (t == 0) {
#pragma unroll
        for (int i = 0; i < 8; i++) {
            int row = warpM * 64 + (i >> 1) * 16 + g + (i & 1) * 8;
            atomicAdd(&sm[F_L + row], rs[i]);
        }
    }
    __syncthreads();
    if (tid < 128) sm[F_INV + tid] = 1.0f / sm[F_L + tid];
    __syncthreads();

    // ---------------- Phase 2: attn write (coalesced) + P@V ----------------
    float o[4][2][4];
#pragma unroll
    for (int i = 0; i < 4; i++)
#pragma unroll
        for (int j = 0; j < 2; j++)
#pragma unroll
            for (int kk = 0; kk < 4; kk++) o[i][j][kk] = 0.0f;

    float* Ps = sm + F_P;
    const float* invl = sm + F_INV;
    const float* Kb = sm + F_A;
    const float* Vb = sm + F_B;

    // store mapping: 128 rows x 16 float4 columns, 8 rows per thread
    const int st_r0 = tid >> 4, st_c = (tid & 15) * 4;

    for (int c = 0; c < ntiles; c++) {
        // K(c) ready (V(c) is the newest pending group)
        CP_WAIT1();
        __syncthreads();

        float cs[4][2][4];
#pragma unroll
        for (int i = 0; i < 4; i++)
#pragma unroll
            for (int j = 0; j < 2; j++)
#pragma unroll
                for (int kk = 0; kk < 4; kk++) cs[i][j][kk] = 0.0f;

#pragma unroll
        for (int kk = 0; kk < 64; kk += 8) {
            uint32_t af[4][4], bf[2][2];
#pragma unroll
            for (int mt = 0; mt < 4; mt++) {
                int r0 = warpM * 64 + mt * 16 + g;
                af[mt][0] = tf32b(Qs[r0 * F_ST + kk + t]);
                af[mt][1] = tf32b(Qs[(r0 + 8) * F_ST + kk + t]);
                af[mt][2] = tf32b(Qs[r0 * F_ST + kk + t + 4]);
                af[mt][3] = tf32b(Qs[(r0 + 8) * F_ST + kk + t + 4]);
            }
#pragma unroll
            for (int nt = 0; nt < 2; nt++) {
                int n0 = warpN * 16 + nt * 8 + g;
                bf[nt][0] = tf32b(Kb[n0 * F_ST + kk + t]);
                bf[nt][1] = tf32b(Kb[n0 * F_ST + kk + t + 4]);
            }
#pragma unroll
            for (int mt = 0; mt < 4; mt++)
#pragma unroll
                for (int nt = 0; nt < 2; nt++)
                    mma_tf32(cs[mt][nt], af[mt], bf[nt]);
        }

        // all warps done reading K buf -> prefetch K(c+1) into A
        __syncthreads();
        if (c + 1 < ntiles) { issueK(c + 1, F_A); CP_COMMIT(); }

        // P = exp(S)*inv_l -> smem Ps  (overlaps K(c+1) load)
        if (c < 2 * qt) {
#pragma unroll
            for (int mt = 0; mt < 4; mt++)
#pragma unroll
                for (int half = 0; half < 2; half++) {
                    int rloc = warpM * 64 + mt * 16 + g + half * 8;
                    float inv = invl[rloc];
#pragma unroll
                    for (int nt = 0; nt < 2; nt++) {
                        int klc = warpN * 16 + nt * 8 + 2 * t;
                        float p0 = __expf(cs[mt][nt][half * 2] * SCALE_F) * inv;
                        float p1 = __expf(cs[mt][nt][half * 2 + 1] * SCALE_F) * inv;
                        *(float2*)&Ps[rloc * F_ST + klc] = make_float2(p0, p1);
                    }
                }
        } else {
#pragma unroll
            for (int mt = 0; mt < 4; mt++)
#pragma unroll
                for (int half = 0; half < 2; half++) {
                    int rloc = warpM * 64 + mt * 16 + g + half * 8;
                    int qi = qt * 128 + rloc;
                    float inv = invl[rloc];
#pragma unroll
                    for (int nt = 0; nt < 2; nt++) {
                        int klc = warpN * 16 + nt * 8 + 2 * t;
                        int kj = c * 64 + klc;
                        float p0 = (kj <= qi) ? __expf(cs[mt][nt][half * 2] * SCALE_F) * inv : 0.0f;
                        float p1 = (kj + 1 <= qi) ? __expf(cs[mt][nt][half * 2 + 1] * SCALE_F) * inv : 0.0f;
                        *(float2*)&Ps[rloc * F_ST + klc] = make_float2(p0, p1);
                    }
                }
        }

        // V(c) ready
        if (c + 1 < ntiles) CP_WAIT1(); else CP_WAIT0();
        __syncthreads();   // Ps visible + V ready

        // coalesced attn store from Ps (fire-and-forget, overlaps PV mma issue)
        {
            float* dst = attn_base + c * 64 + st_c;
#pragma unroll
            for (int j = 0; j < 8; j++) {
                int r = st_r0 + j * 16;
                *(float4*)(dst + (size_t)r * Sn) = *(const float4*)&Ps[r * F_ST + st_c];
            }
        }

        // O += P @ V
#pragma unroll
        for (int kk = 0; kk < 64; kk += 8) {
            uint32_t af[4][4], bf[2][2];
#pragma unroll
            for (int mt = 0; mt < 4; mt++) {
                int r0 = warpM * 64 + mt * 16 + g;
                af[mt][0] = tf32b(Ps[r0 * F_ST + kk + t]);
                af[mt][1] = tf32b(Ps[(r0 + 8) * F_ST + kk + t]);
                af[mt][2] = tf32b(Ps[r0 * F_ST + kk + t + 4]);
                af[mt][3] = tf32b(Ps[(r0 + 8) * F_ST + kk + t + 4]);
            }
#pragma unroll
            for (int nt = 0; nt < 2; nt++) {
                int n0 = warpN * 16 + nt * 8 + g;
                bf[nt][0] = tf32b(Vb[(kk + t) * F_ST + n0]);
                bf[nt][1] = tf32b(Vb[(kk + t + 4) * F_ST + n0]);
            }
#pragma unroll
            for (int mt = 0; mt < 4; mt++)
#pragma unroll
                for (int nt = 0; nt < 2; nt++)
                    mma_tf32(o[mt][nt], af[mt], bf[nt]);
        }

        // all warps done reading V buf -> prefetch V(c+1) into B
        __syncthreads();
        if (c + 1 < ntiles) { issueV(c + 1, F_B); CP_COMMIT(); }
    }

    // write O to ctx [B,S,H*DH]
#pragma unroll
    for (int mt = 0; mt < 4; mt++) {
#pragma unroll
        for (int nt = 0; nt < 2; nt++) {
            int s0 = qt * 128 + warpM * 64 + mt * 16 + g;
            int d0 = warpN * 16 + nt * 8 + 2 * t;
#pragma unroll
            for (int half = 0; half < 2; half++) {
                int s = s0 + half * 8;
                size_t base = ((size_t)b * Sn + s) * Dn + h * DHn + d0;
                ctx[base] = o[mt][nt][half * 2 + 0];
                ctx[base + 1] = o[mt][nt][half * 2 + 1];
            }
        }
    }
}

// ---------------------------------------------------------------------------
// Launch
// ---------------------------------------------------------------------------
extern "C" void kernel_launch(void* const* d_in, const int* in_sizes, int n_in,
                              void* d_out, int out_size)
{
    const float* Q  = (const float*)d_in[0];
    const float* K  = (const float*)d_in[1];
    const float* V  = (const float*)d_in[2];
    const float* wq = (const float*)d_in[4];
    const float* bq = (const float*)d_in[5];
    const float* wk = (const float*)d_in[6];
    const float* bk = (const float*)d_in[7];
    const float* wv = (const float*)d_in[8];
    const float* bv = (const float*)d_in[9];
    const float* wo = (const float*)d_in[10];
    const float* bo = (const float*)d_in[11];

    float* out = (float*)d_out;

    float* attn;
    if ((size_t)out_size >= OUT_ELEMS + ATTN_ELEMS) {
        attn = out + OUT_ELEMS;
    } else {
        void* p = nullptr;
        cudaGetSymbolAddress(&p, g_attn_scratch);
        attn = (float*)p;
    }

    float *gq, *gk, *gv, *gctx;
    {
        void* p;
        cudaGetSymbolAddress(&p, g_q);   gq   = (float*)p;
        cudaGetSymbolAddress(&p, g_k);   gk   = (float*)p;
        cudaGetSymbolAddress(&p, g_v);   gv   = (float*)p;
        cudaGetSymbolAddress(&p, g_ctx); gctx = (float*)p;
    }

    cudaFuncSetAttribute(tf32_gemm_kernel,
                         cudaFuncAttributeMaxDynamicSharedMemorySize, GEMM_SMEM);
    cudaFuncSetAttribute(fused_attn_kernel,
                         cudaFuncAttributeMaxDynamicSharedMemorySize, FUSED_SMEM);

    // QKV projections in one launch (grid.z selects which)
    dim3 gqkv(Dn / 128, Mn / 128, 3);   // (8, 64, 3)
    tf32_gemm_kernel<<<gqkv, 256, GEMM_SMEM>>>(
        Q, K, V, wq, wk, wv, bq, bk, bv, gq, gk, gv, 1);

    fused_attn_kernel<<<dim3(NQT, BHn), 256, FUSED_SMEM>>>(gq, gk, gv, attn, gctx);

    // output projection
    dim3 go(Dn / 128, Mn / 128, 1);
    tf32_gemm_kernel<<<go, 256, GEMM_SMEM>>>(
        gctx, gctx, gctx, wo, wo, wo, bo, bo, bo, out, out, out, 0);
}

// round 12
// speedup vs baseline: 1.0868x; 1.0355x over previous
#include <cuda_runtime.h>
#include <cstdint>
#include <math.h>

// Problem constants
#define Bn   4
#define Sn   2048
#define Dn   1024
#define Hn   16
#define DHn  64
#define BHn  (Bn * Hn)          // 64
#define Mn   (Bn * Sn)          // 8192
#define NQT  (Sn / 128)         // 16 q-tiles
#define SCALE_F 0.125f

#define OUT_ELEMS  ((size_t)Mn * Dn)            // 8,388,608
#define ATTN_ELEMS ((size_t)BHn * Sn * Sn)      // 268,435,456

// Scratch (device globals)
__device__ float g_q[Mn * Dn];            // [B,H,S,DH] (tf32-rounded)
__device__ float g_k[Mn * Dn];
__device__ float g_v[Mn * Dn];
__device__ float g_ctx[Mn * Dn];          // [B,S,H*DH] (tf32-rounded)
__device__ float g_qc[Mn * Dn];           // tf32-rounded inputs
__device__ float g_kc[Mn * Dn];
__device__ float g_vc[Mn * Dn];
__device__ float g_wc[4][Dn * Dn];        // tf32-rounded weights
__device__ float g_attn_scratch[ATTN_ELEMS];

// ---------------------------------------------------------------------------
// PTX helpers
// ---------------------------------------------------------------------------
__device__ __forceinline__ uint32_t smem_u32(const void* p) {
    uint32_t a;
    asm("{ .reg .u64 t; cvta.to.shared.u64 t, %1; cvt.u32.u64 %0, t; }" : "=r"(a) : "l"(p));
    return a;
}
#define CP16(dst, src) \
    asm volatile("cp.async.cg.shared.global [%0], [%1], 16;" :: "r"(dst), "l"(src))
#define CP_COMMIT() asm volatile("cp.async.commit_group;")
#define CP_WAIT1()  asm volatile("cp.async.wait_group 1;")
#define CP_WAIT0()  asm volatile("cp.async.wait_group 0;")

__device__ __forceinline__ float tf32r(float f) {
    uint32_t r; asm("cvt.rna.tf32.f32 %0, %1;" : "=r"(r) : "f"(f));
    return __uint_as_float(r);
}
__device__ __forceinline__ void mma_tf32(float c[4], const uint32_t a[4], const uint32_t b[2]) {
    asm volatile(
        "mma.sync.aligned.m16n8k8.row.col.f32.tf32.tf32.f32 "
        "{%0,%1,%2,%3}, {%4,%5,%6,%7}, {%8,%9}, {%0,%1,%2,%3};"
        : "+f"(c[0]), "+f"(c[1]), "+f"(c[2]), "+f"(c[3])
        : "r"(a[0]), "r"(a[1]), "r"(a[2]), "r"(a[3]), "r"(b[0]), "r"(b[1]));
}
__device__ __forceinline__ uint32_t fbits(float f) { return __float_as_uint(f); }

// ---------------------------------------------------------------------------
// tf32 pre-round: out[i] = round_tf32(in[i]), float4 grid-stride
// ---------------------------------------------------------------------------
__global__ __launch_bounds__(256) void tf32_round_kernel(
    const float* __restrict__ in, float* __restrict__ out, int n4)
{
    int i = blockIdx.x * 256 + threadIdx.x;
    if (i < n4) {
        float4 v = ((const float4*)in)[i];
        v.x = tf32r(v.x); v.y = tf32r(v.y); v.z = tf32r(v.z); v.w = tf32r(v.w);
        ((float4*)out)[i] = v;
    }
}

// ---------------------------------------------------------------------------
// tf32 mma GEMM, 2-stage pipeline, 2 CTAs/SM. QKV fused via blockIdx.z.
// Inputs already tf32-rounded -> NO cvt in the hot loop.
// mode 1 epilogue stores tf32-rounded (so consumers skip cvt too).
// ---------------------------------------------------------------------------
#define G_AST 36
#define G_BST 132
#define G_STAGE_F (128 * G_AST + 32 * G_BST)
#define GEMM_SMEM (2 * G_STAGE_F * 4)        // 70,656 bytes

__global__ __launch_bounds__(256, 2) void tf32_gemm_kernel(
    const float* __restrict__ X0, const float* __restrict__ X1, const float* __restrict__ X2,
    const float* __restrict__ W0, const float* __restrict__ W1, const float* __restrict__ W2,
    const float* __restrict__ B0, const float* __restrict__ B1, const float* __restrict__ B2,
    float* __restrict__ O0, float* __restrict__ O1, float* __restrict__ O2,
    int mode)
{
    extern __shared__ float sm[];
    const int z = blockIdx.z;
    const float* X    = (z == 0) ? X0 : (z == 1) ? X1 : X2;
    const float* W    = (z == 0) ? W0 : (z == 1) ? W1 : W2;
    const float* bias = (z == 0) ? B0 : (z == 1) ? B1 : B2;
    float* out        = (z == 0) ? O0 : (z == 1) ? O1 : O2;

    const int tid = threadIdx.x;
    const int wid = tid >> 5, lane = tid & 31;
    const int g = lane >> 2, t = lane & 3;
    const int warpM = wid & 1, warpN = wid >> 1;
    const int bm = blockIdx.y * 128, bn = blockIdx.x * 128;

    const uint32_t sbase = smem_u32(sm);

    float c[4][4][4];
#pragma unroll
    for (int i = 0; i < 4; i++)
#pragma unroll
        for (int j = 0; j < 4; j++)
#pragma unroll
            for (int k = 0; k < 4; k++) c[i][j][k] = 0.0f;

    auto issue = [&](int cidx, int buf) {
        const float* Xp = X + (size_t)bm * Dn + cidx * 32;
        const float* Wp = W + (size_t)(cidx * 32) * Dn + bn;
        uint32_t abase = sbase + buf * (G_STAGE_F * 4);
        uint32_t bbase = abase + 128 * G_AST * 4;
#pragma unroll
        for (int j = 0; j < 4; j++) {
            int ia = tid + j * 256;
            int ar = ia >> 3, ac = ia & 7;
            CP16(abase + ar * (G_AST * 4) + ac * 16, Xp + (size_t)ar * Dn + ac * 4);
            int br = ia >> 5, bc = ia & 31;
            CP16(bbase + br * (G_BST * 4) + bc * 16, Wp + (size_t)br * Dn + bc * 4);
        }
    };

    issue(0, 0); CP_COMMIT();

    const int NCH = Dn / 32;   // 32
    for (int s = 0; s < NCH; s++) {
        CP_WAIT0();
        __syncthreads();
        if (s + 1 < NCH) { issue(s + 1, (s + 1) & 1); CP_COMMIT(); }

        const float* A = sm + (s & 1) * G_STAGE_F;
        const float* B = A + 128 * G_AST;
#pragma unroll
        for (int kk = 0; kk < 32; kk += 8) {
            uint32_t af[4][4], bf[4][2];
#pragma unroll
            for (int mt = 0; mt < 4; mt++) {
                int r0 = warpM * 64 + mt * 16 + g;
                af[mt][0] = fbits(A[r0 * G_AST + kk + t]);
                af[mt][1] = fbits(A[(r0 + 8) * G_AST + kk + t]);
                af[mt][2] = fbits(A[r0 * G_AST + kk + t + 4]);
                af[mt][3] = fbits(A[(r0 + 8) * G_AST + kk + t + 4]);
            }
#pragma unroll
            for (int nt = 0; nt < 4; nt++) {
                int n0 = warpN * 32 + nt * 8 + g;
                bf[nt][0] = fbits(B[(kk + t) * G_BST + n0]);
                bf[nt][1] = fbits(B[(kk + t + 4) * G_BST + n0]);
            }
#pragma unroll
            for (int mt = 0; mt < 4; mt++)
#pragma unroll
                for (int nt = 0; nt < 4; nt++)
                    mma_tf32(c[mt][nt], af[mt], bf[nt]);
        }
    }

#pragma unroll
    for (int mt = 0; mt < 4; mt++) {
#pragma unroll
        for (int nt = 0; nt < 4; nt++) {
            int m0 = bm + warpM * 64 + mt * 16 + g;
            int n0 = bn + warpN * 32 + nt * 8 + 2 * t;
#pragma unroll
            for (int half = 0; half < 2; half++) {
                int m = m0 + half * 8;
                float v0 = c[mt][nt][half * 2 + 0] + bias[n0];
                float v1 = c[mt][nt][half * 2 + 1] + bias[n0 + 1];
                if (mode == 0) {
                    out[(size_t)m * Dn + n0] = v0;
                    out[(size_t)m * Dn + n0 + 1] = v1;
                } else {
                    int b = m >> 11, sq = m & (Sn - 1);
                    int h = n0 >> 6, d = n0 & 63;
                    size_t base = (((size_t)b * Hn + h) * Sn + sq) * DHn + d;
                    out[base] = tf32r(v0);
                    out[base + 1] = tf32r(v1);
                }
            }
        }
    }
}

// ---------------------------------------------------------------------------
// Fused attention, 2 CTAs/SM. All operands pre-rounded -> no cvt in loops.
// ---------------------------------------------------------------------------
#define F_ST   68
#define F_Q    0                          // 128 x 68
#define F_A    (128 * F_ST)               // 64 x 68
#define F_B    (F_A + 64 * F_ST)          // 64 x 68
#define F_P    (F_B + 64 * F_ST)          // 128 x 68
#define F_L    (F_P + 128 * F_ST)         // 128
#define F_INV  (F_L + 128)                // 128
#define FUSED_SMEM ((F_INV + 128) * 4)    // 105,472 bytes

__global__ __launch_bounds__(256, 2) void fused_attn_kernel(
    const float* __restrict__ q, const float* __restrict__ k,
    const float* __restrict__ v, float* __restrict__ attn,
    float* __restrict__ ctx)
{
    extern __shared__ float sm[];
    const int bh = blockIdx.y;
    const int qt = (NQT - 1) - blockIdx.x;   // heavy tiles first
    const int b = bh >> 4, h = bh & 15;

    const int tid = threadIdx.x;
    const int wid = tid >> 5, lane = tid & 31;
    const int g = lane >> 2, t = lane & 3;
    const int warpM = wid & 1, warpN = wid >> 1;   // 2 x 4

    const uint32_t sbase = smem_u32(sm);
    const float* qb = q + ((size_t)bh * Sn + qt * 128) * DHn;
    const float* kbase = k + (size_t)bh * Sn * DHn;
    const float* vbase = v + (size_t)bh * Sn * DHn;
    float* attn_base = attn + ((size_t)bh * Sn + qt * 128) * Sn;

    const int ntiles = 2 * (qt + 1);   // 64-row K/V tiles

    auto issueK = [&](int c, uint32_t bufoff) {
        const float* kb = kbase + (size_t)(c * 64) * DHn;
        uint32_t dst = sbase + bufoff * 4;
#pragma unroll
        for (int j = 0; j < 4; j++) {
            int ia = tid + j * 256;
            int r = ia >> 4, c4 = ia & 15;
            CP16(dst + r * (F_ST * 4) + c4 * 16, kb + (size_t)r * DHn + c4 * 4);
        }
    };
    auto issueV = [&](int c, uint32_t bufoff) {
        const float* vb = vbase + (size_t)(c * 64) * DHn;
        uint32_t dst = sbase + bufoff * 4;
#pragma unroll
        for (int j = 0; j < 4; j++) {
            int ia = tid + j * 256;
            int r = ia >> 4, c4 = ia & 15;
            CP16(dst + r * (F_ST * 4) + c4 * 16, vb + (size_t)r * DHn + c4 * 4);
        }
    };

    // Q load + first K tile
    {
        uint32_t qdst = sbase + F_Q * 4;
#pragma unroll
        for (int j = 0; j < 8; j++) {
            int ia = tid + j * 256;
            int r = ia >> 4, c4 = ia & 15;
            CP16(qdst + r * (F_ST * 4) + c4 * 16, qb + (size_t)r * DHn + c4 * 4);
        }
        issueK(0, F_A);
        CP_COMMIT();
    }

    // zero-fill causal upper region (overlaps async loads)
    {
        int zc0 = (qt + 1) * 128;
        int nz4 = (Sn - zc0) >> 2;
        if (nz4 > 0) {
            const float4 z = make_float4(0.f, 0.f, 0.f, 0.f);
            for (int idx = tid; idx < 128 * nz4; idx += 256) {
                int r = idx / nz4, cc = idx - r * nz4;
                *(float4*)(attn_base + (size_t)r * Sn + zc0 + cc * 4) = z;
            }
        }
    }

    if (tid < 128) sm[F_L + tid] = 0.0f;

    const float* Qs = sm + F_Q;

    // ---------------- Phase 1: row sums of exp(S) ----------------
    float rs[8];
#pragma unroll
    for (int i = 0; i < 8; i++) rs[i] = 0.0f;

    for (int c = 0; c < ntiles; c++) {
        CP_WAIT0();
        __syncthreads();
        if (c + 1 < ntiles) {
            issueK(c + 1, ((c + 1) & 1) ? F_B : F_A);
            CP_COMMIT();
        }

        const float* K = sm + ((c & 1) ? F_B : F_A);
        float cs[4][2][4];
#pragma unroll
        for (int i = 0; i < 4; i++)
#pragma unroll
            for (int j = 0; j < 2; j++)
#pragma unroll
                for (int kk = 0; kk < 4; kk++) cs[i][j][kk] = 0.0f;

#pragma unroll
        for (int kk = 0; kk < 64; kk += 8) {
            uint32_t af[4][4], bf[2][2];
#pragma unroll
            for (int mt = 0; mt < 4; mt++) {
                int r0 = warpM * 64 + mt * 16 + g;
                af[mt][0] = fbits(Qs[r0 * F_ST + kk + t]);
                af[mt][1] = fbits(Qs[(r0 + 8) * F_ST + kk + t]);
                af[mt][2] = fbits(Qs[r0 * F_ST + kk + t + 4]);
                af[mt][3] = fbits(Qs[(r0 + 8) * F_ST + kk + t + 4]);
            }
#pragma unroll
            for (int nt = 0; nt < 2; nt++) {
                int n0 = warpN * 16 + nt * 8 + g;
                bf[nt][0] = fbits(K[n0 * F_ST + kk + t]);
                bf[nt][1] = fbits(K[n0 * F_ST + kk + t + 4]);
            }
#pragma unroll
            for (int mt = 0; mt < 4; mt++)
#pragma unroll
                for (int nt = 0; nt < 2; nt++)
                    mma_tf32(cs[mt][nt], af[mt], bf[nt]);
        }

        if (c < 2 * qt) {
#pragma unroll
            for (int mt = 0; mt < 4; mt++)
#pragma unroll
                for (int half = 0; half < 2; half++) {
                    float acc = 0.0f;
#pragma unroll
                    for (int nt = 0; nt < 2; nt++) {
                        acc += __expf(cs[mt][nt][half * 2] * SCALE_F);
                        acc += __expf(cs[mt][nt][half * 2 + 1] * SCALE_F);
                    }
                    rs[mt * 2 + half] += acc;
                }
        } else {
#pragma unroll
            for (int mt = 0; mt < 4; mt++)
#pragma unroll
                for (int half = 0; half < 2; half++) {
                    int qi = qt * 128 + warpM * 64 + mt * 16 + g + half * 8;
                    float acc = 0.0f;
#pragma unroll
                    for (int nt = 0; nt < 2; nt++) {
                        int kj = c * 64 + warpN * 16 + nt * 8 + 2 * t;
                        if (kj <= qi)     acc += __expf(cs[mt][nt][half * 2] * SCALE_F);
                        if (kj + 1 <= qi) acc += __expf(cs[mt][nt][half * 2 + 1] * SCALE_F);
                    }
                    rs[mt * 2 + half] += acc;
                }
        }
    }

    // all warps done with bufs; prefetch phase-2 tiles, then reduce row sums
    __syncthreads();
    issueK(0, F_A); CP_COMMIT();
    issueV(0, F_B); CP_COMMIT();

#pragma unroll
    for (int i = 0; i < 8; i++) {
        rs[i] += __shfl_xor_sync(0xffffffffu, rs[i], 1);
        rs[i] += __shfl_xor_sync(0xffffffffu, rs[i], 2);
    }
    if (t == 0) {
#pragma unroll
        for (int i = 0; i < 8; i++) {
            int row = warpM * 64 + (i >> 1) * 16 + g + (i & 1) * 8;
            atomicAdd(&sm[F_L + row], rs[i]);
        }
    }
    __syncthreads();
    if (tid < 128) sm[F_INV + tid] = 1.0f / sm[F_L + tid];
    __syncthreads();

    // ---------------- Phase 2: attn write (coalesced) + P@V ----------------
    float o[4][2][4];
#pragma unroll
    for (int i = 0; i < 4; i++)
#pragma unroll
        for (int j = 0; j < 2; j++)
#pragma unroll
            for (int kk = 0; kk < 4; kk++) o[i][j][kk] = 0.0f;

    float* Ps = sm + F_P;
    const float* invl = sm + F_INV;
    const float* Kb = sm + F_A;
    const float* Vb = sm + F_B;

    const int st_r0 = tid >> 4, st_c = (tid & 15) * 4;

    for (int c = 0; c < ntiles; c++) {
        CP_WAIT1();
        __syncthreads();

        float cs[4][2][4];
#pragma unroll
        for (int i = 0; i < 4; i++)
#pragma unroll
            for (int j = 0; j < 2; j++)
#pragma unroll
                for (int kk = 0; kk < 4; kk++) cs[i][j][kk] = 0.0f;

#pragma unroll
        for (int kk = 0; kk < 64; kk += 8) {
            uint32_t af[4][4], bf[2][2];
#pragma unroll
            for (int mt = 0; mt < 4; mt++) {
                int r0 = warpM * 64 + mt * 16 + g;
                af[mt][0] = fbits(Qs[r0 * F_ST + kk + t]);
                af[mt][1] = fbits(Qs[(r0 + 8) * F_ST + kk + t]);
                af[mt][2] = fbits(Qs[r0 * F_ST + kk + t + 4]);
                af[mt][3] = fbits(Qs[(r0 + 8) * F_ST + kk + t + 4]);
            }
#pragma unroll
            for (int nt = 0; nt < 2; nt++) {
                int n0 = warpN * 16 + nt * 8 + g;
                bf[nt][0] = fbits(Kb[n0 * F_ST + kk + t]);
                bf[nt][1] = fbits(Kb[n0 * F_ST + kk + t + 4]);
            }
#pragma unroll
            for (int mt = 0; mt < 4; mt++)
#pragma unroll
                for (int nt = 0; nt < 2; nt++)
                    mma_tf32(cs[mt][nt], af[mt], bf[nt]);
        }

        __syncthreads();
        if (c + 1 < ntiles) { issueK(c + 1, F_A); CP_COMMIT(); }

        // P = round_tf32(exp(S)*inv_l) -> smem Ps (overlaps K(c+1) load)
        if (c < 2 * qt) {
#pragma unroll
            for (int mt = 0; mt < 4; mt++)
#pragma unroll
                for (int half = 0; half < 2; half++) {
                    int rloc = warpM * 64 + mt * 16 + g + half * 8;
                    float inv = invl[rloc];
#pragma unroll
                    for (int nt = 0; nt < 2; nt++) {
                        int klc = warpN * 16 + nt * 8 + 2 * t;
                        float p0 = tf32r(__expf(cs[mt][nt][half * 2] * SCALE_F) * inv);
                        float p1 = tf32r(__expf(cs[mt][nt][half * 2 + 1] * SCALE_F) * inv);
                        *(float2*)&Ps[rloc * F_ST + klc] = make_float2(p0, p1);
                    }
                }
        } else {
#pragma unroll
            for (int mt = 0; mt < 4; mt++)
#pragma unroll
                for (int half = 0; half < 2; half++) {
                    int rloc = warpM * 64 + mt * 16 + g + half * 8;
                    int qi = qt * 128 + rloc;
                    float inv = invl[rloc];
#pragma unroll
                    for (int nt = 0; nt < 2; nt++) {
                        int klc = warpN * 16 + nt * 8 + 2 * t;
                        int kj = c * 64 + klc;
                        float p0 = (kj <= qi) ? tf32r(__expf(cs[mt][nt][half * 2] * SCALE_F) * inv) : 0.0f;
                        float p1 = (kj + 1 <= qi) ? tf32r(__expf(cs[mt][nt][half * 2 + 1] * SCALE_F) * inv) : 0.0f;
                        *(float2*)&Ps[rloc * F_ST + klc] = make_float2(p0, p1);
                    }
                }
        }

        // V(c) ready
        if (c + 1 < ntiles) CP_WAIT1(); else CP_WAIT0();
        __syncthreads();   // Ps visible + V ready

        // coalesced attn store from Ps
        {
            float* dst = attn_base + c * 64 + st_c;
#pragma unroll
            for (int j = 0; j < 8; j++) {
                int r = st_r0 + j * 16;
                *(float4*)(dst + (size_t)r * Sn) = *(const float4*)&Ps[r * F_ST + st_c];
            }
        }

        // O += P @ V
#pragma unroll
        for (int kk = 0; kk < 64; kk += 8) {
            uint32_t af[4][4], bf[2][2];
#pragma unroll
            for (int mt = 0; mt < 4; mt++) {
                int r0 = warpM * 64 + mt * 16 + g;
                af[mt][0] = fbits(Ps[r0 * F_ST + kk + t]);
                af[mt][1] = fbits(Ps[(r0 + 8) * F_ST + kk + t]);
                af[mt][2] = fbits(Ps[r0 * F_ST + kk + t + 4]);
                af[mt][3] = fbits(Ps[(r0 + 8) * F_ST + kk + t + 4]);
            }
#pragma unroll
            for (int nt = 0; nt < 2; nt++) {
                int n0 = warpN * 16 + nt * 8 + g;
                bf[nt][0] = fbits(Vb[(kk + t) * F_ST + n0]);
                bf[nt][1] = fbits(Vb[(kk + t + 4) * F_ST + n0]);
            }
#pragma unroll
            for (int mt = 0; mt < 4; mt++)
#pragma unroll
                for (int nt = 0; nt < 2; nt++)
                    mma_tf32(o[mt][nt], af[mt], bf[nt]);
        }

        __syncthreads();
        if (c + 1 < ntiles) { issueV(c + 1, F_B); CP_COMMIT(); }
    }

    // write O to ctx [B,S,H*DH], tf32-rounded (out-proj reads raw bits)
#pragma unroll
    for (int mt = 0; mt < 4; mt++) {
#pragma unroll
        for (int nt = 0; nt < 2; nt++) {
            int s0 = qt * 128 + warpM * 64 + mt * 16 + g;
            int d0 = warpN * 16 + nt * 8 + 2 * t;
#pragma unroll
            for (int half = 0; half < 2; half++) {
                int s = s0 + half * 8;
                size_t base = ((size_t)b * Sn + s) * Dn + h * DHn + d0;
                ctx[base] = tf32r(o[mt][nt][half * 2 + 0]);
                ctx[base + 1] = tf32r(o[mt][nt][half * 2 + 1]);
            }
        }
    }
}

// ---------------------------------------------------------------------------
// Launch
// ---------------------------------------------------------------------------
extern "C" void kernel_launch(void* const* d_in, const int* in_sizes, int n_in,
                              void* d_out, int out_size)
{
    const float* Q  = (const float*)d_in[0];
    const float* K  = (const float*)d_in[1];
    const float* V  = (const float*)d_in[2];
    const float* wq = (const float*)d_in[4];
    const float* bq = (const float*)d_in[5];
    const float* wk = (const float*)d_in[6];
    const float* bk = (const float*)d_in[7];
    const float* wv = (const float*)d_in[8];
    const float* bv = (const float*)d_in[9];
    const float* wo = (const float*)d_in[10];
    const float* bo = (const float*)d_in[11];

    float* out = (float*)d_out;

    float* attn;
    if ((size_t)out_size >= OUT_ELEMS + ATTN_ELEMS) {
        attn = out + OUT_ELEMS;
    } else {
        void* p = nullptr;
        cudaGetSymbolAddress(&p, g_attn_scratch);
        attn = (float*)p;
    }

    float *gq, *gk, *gv, *gctx, *gqc, *gkc, *gvc, *gwc;
    {
        void* p;
        cudaGetSymbolAddress(&p, g_q);   gq   = (float*)p;
        cudaGetSymbolAddress(&p, g_k);   gk   = (float*)p;
        cudaGetSymbolAddress(&p, g_v);   gv   = (float*)p;
        cudaGetSymbolAddress(&p, g_ctx); gctx = (float*)p;
        cudaGetSymbolAddress(&p, g_qc);  gqc  = (float*)p;
        cudaGetSymbolAddress(&p, g_kc);  gkc  = (float*)p;
        cudaGetSymbolAddress(&p, g_vc);  gvc  = (float*)p;
        cudaGetSymbolAddress(&p, g_wc);  gwc  = (float*)p;
    }
    float* wcq = gwc;
    float* wck = gwc + (size_t)Dn * Dn;
    float* wcv = gwc + 2 * (size_t)Dn * Dn;
    float* wco = gwc + 3 * (size_t)Dn * Dn;

    cudaFuncSetAttribute(tf32_gemm_kernel,
                         cudaFuncAttributeMaxDynamicSharedMemorySize, GEMM_SMEM);
    cudaFuncSetAttribute(fused_attn_kernel,
                         cudaFuncAttributeMaxDynamicSharedMemorySize, FUSED_SMEM);

    // pre-round inputs + weights to tf32
    const int n4_big = (Mn * Dn) / 4;      // 2,097,152
    const int n4_w   = (Dn * Dn) / 4;      // 262,144
    tf32_round_kernel<<<(n4_big + 255) / 256, 256>>>(Q, gqc, n4_big);
    tf32_round_kernel<<<(n4_big + 255) / 256, 256>>>(K, gkc, n4_big);
    tf32_round_kernel<<<(n4_big + 255) / 256, 256>>>(V, gvc, n4_big);
    tf32_round_kernel<<<(n4_w + 255) / 256, 256>>>(wq, wcq, n4_w);
    tf32_round_kernel<<<(n4_w + 255) / 256, 256>>>(wk, wck, n4_w);
    tf32_round_kernel<<<(n4_w + 255) / 256, 256>>>(wv, wcv, n4_w);
    tf32_round_kernel<<<(n4_w + 255) / 256, 256>>>(wo, wco, n4_w);

    // QKV projections in one launch (grid.z selects which)
    dim3 gqkv(Dn / 128, Mn / 128, 3);   // (8, 64, 3)
    tf32_gemm_kernel<<<gqkv, 256, GEMM_SMEM>>>(
        gqc, gkc, gvc, wcq, wck, wcv, bq, bk, bv, gq, gk, gv, 1);

    fused_attn_kernel<<<dim3(NQT, BHn), 256, FUSED_SMEM>>>(gq, gk, gv, attn, gctx);

    // output projection
    dim3 go(Dn / 128, Mn / 128, 1);
    tf32_gemm_kernel<<<go, 256, GEMM_SMEM>>>(
        gctx, gctx, gctx, wco, wco, wco, bo, bo, bo, out, out, out, 0);
}

// round 13
// speedup vs baseline: 1.1456x; 1.0541x over previous
#include <cuda_runtime.h>
#include <cstdint>
#include <math.h>

// Problem constants
#define Bn   4
#define Sn   2048
#define Dn   1024
#define Hn   16
#define DHn  64
#define BHn  (Bn * Hn)          // 64
#define Mn   (Bn * Sn)          // 8192
#define NQT  (Sn / 128)         // 16 q-tiles
#define SCALE_F 0.125f

#define OUT_ELEMS  ((size_t)Mn * Dn)            // 8,388,608
#define ATTN_ELEMS ((size_t)BHn * Sn * Sn)      // 268,435,456

// Scratch (device globals)
__device__ float g_q[Mn * Dn];            // [B,H,S,DH] tf32-rounded, DH pi-permuted
__device__ float g_k[Mn * Dn];
__device__ float g_v[Mn * Dn];
__device__ float g_ctx[Mn * Dn];          // [B,S,H*DH] tf32-rounded, pi-permuted
__device__ float g_qc[Mn * Dn];           // tf32-rounded + k-permuted inputs
__device__ float g_kc[Mn * Dn];
__device__ float g_vc[Mn * Dn];
__device__ float g_wc[4][Dn * Dn];        // weights: transposed [N,K], tf32, k-permuted
__device__ float g_attn_scratch[ATTN_ELEMS];

// ---------------------------------------------------------------------------
// PTX helpers
// ---------------------------------------------------------------------------
__device__ __forceinline__ uint32_t smem_u32(const void* p) {
    uint32_t a;
    asm("{ .reg .u64 t; cvta.to.shared.u64 t, %1; cvt.u32.u64 %0, t; }" : "=r"(a) : "l"(p));
    return a;
}
#define CP16(dst, src) \
    asm volatile("cp.async.cg.shared.global [%0], [%1], 16;" :: "r"(dst), "l"(src))
#define CP_COMMIT() asm volatile("cp.async.commit_group;")
#define CP_WAIT1()  asm volatile("cp.async.wait_group 1;")
#define CP_WAIT0()  asm volatile("cp.async.wait_group 0;")

__device__ __forceinline__ float tf32r(float f) {
    uint32_t r; asm("cvt.rna.tf32.f32 %0, %1;" : "=r"(r) : "f"(f));
    return __uint_as_float(r);
}
__device__ __forceinline__ void mma_tf32(float c[4], const uint32_t a[4], const uint32_t b[2]) {
    asm volatile(
        "mma.sync.aligned.m16n8k8.row.col.f32.tf32.tf32.f32 "
        "{%0,%1,%2,%3}, {%4,%5,%6,%7}, {%8,%9}, {%0,%1,%2,%3};"
        : "+f"(c[0]), "+f"(c[1]), "+f"(c[2]), "+f"(c[3])
        : "r"(a[0]), "r"(a[1]), "r"(a[2]), "r"(a[3]), "r"(b[0]), "r"(b[1]));
}
__device__ __forceinline__ uint32_t fbits(float f) { return __float_as_uint(f); }
// pi: logical l (0..7) -> physical slot. phys(2i)=l_i, phys(2i+1)=l_{i+4}
__device__ __forceinline__ int pkmap(int l) { return (l < 4) ? (2 * l) : (2 * (l - 4) + 1); }

// ---------------------------------------------------------------------------
// round + k-permute (within aligned 8-groups): out[pi(k)] = tf32(in[k])
// thread handles one 8-group (two float4 reads/writes)
// ---------------------------------------------------------------------------
__global__ __launch_bounds__(256) void round_perm_kernel(
    const float* __restrict__ in, float* __restrict__ out, int n8)
{
    int i = blockIdx.x * 256 + threadIdx.x;
    if (i < n8) {
        const float4* p = (const float4*)in + (size_t)i * 2;
        float4 a = p[0], b = p[1];   // logical 0-3, 4-7
        float4 o0 = make_float4(tf32r(a.x), tf32r(b.x), tf32r(a.y), tf32r(b.y));
        float4 o1 = make_float4(tf32r(a.z), tf32r(b.z), tf32r(a.w), tf32r(b.w));
        float4* q = (float4*)out + (size_t)i * 2;
        q[0] = o0; q[1] = o1;
    }
}

// ---------------------------------------------------------------------------
// weight transpose: W[K,N] -> Wt[N,K], tf32-rounded, k pi-permuted
// ---------------------------------------------------------------------------
__global__ __launch_bounds__(256) void wtrans_kernel(
    const float* __restrict__ in, float* __restrict__ out)
{
    __shared__ float tile[32][33];
    int tx = threadIdx.x, ty = threadIdx.y;
    int k0 = blockIdx.y * 32, n0 = blockIdx.x * 32;
#pragma unroll
    for (int j = 0; j < 32; j += 8)
        tile[ty + j][tx] = in[(size_t)(k0 + ty + j) * Dn + n0 + tx];
    __syncthreads();
    int pk = (tx & ~7) | pkmap(tx & 7);
#pragma unroll
    for (int j = 0; j < 32; j += 8)
        out[(size_t)(n0 + ty + j) * Dn + k0 + pk] = tf32r(tile[tx][ty + j]);
}

// ---------------------------------------------------------------------------
// tf32 mma GEMM: out = X[M,1024] @ Wt[N,K]^T + bias. 2-stage, 2 CTAs/SM.
// X and Wt are pre-rounded + k-permuted -> LDS.64 fragments, no cvt.
// A tile 128x40, B tile 128x40 (n-major).
// ---------------------------------------------------------------------------
#define G_AST 40
#define G_STAGE_F (128 * G_AST * 2)          // 10240 floats
#define GEMM_SMEM (2 * G_STAGE_F * 4)        // 81,920 bytes

__global__ __launch_bounds__(256, 2) void tf32_gemm_kernel(
    const float* __restrict__ X0, const float* __restrict__ X1, const float* __restrict__ X2,
    const float* __restrict__ W0, const float* __restrict__ W1, const float* __restrict__ W2,
    const float* __restrict__ B0, const float* __restrict__ B1, const float* __restrict__ B2,
    float* __restrict__ O0, float* __restrict__ O1, float* __restrict__ O2,
    int mode)
{
    extern __shared__ float sm[];
    const int z = blockIdx.z;
    const float* X    = (z == 0) ? X0 : (z == 1) ? X1 : X2;
    const float* W    = (z == 0) ? W0 : (z == 1) ? W1 : W2;
    const float* bias = (z == 0) ? B0 : (z == 1) ? B1 : B2;
    float* out        = (z == 0) ? O0 : (z == 1) ? O1 : O2;

    const int tid = threadIdx.x;
    const int wid = tid >> 5, lane = tid & 31;
    const int g = lane >> 2, t = lane & 3;
    const int warpM = wid & 1, warpN = wid >> 1;
    const int bm = blockIdx.y * 128, bn = blockIdx.x * 128;

    const uint32_t sbase = smem_u32(sm);

    float c[4][4][4];
#pragma unroll
    for (int i = 0; i < 4; i++)
#pragma unroll
        for (int j = 0; j < 4; j++)
#pragma unroll
            for (int k = 0; k < 4; k++) c[i][j][k] = 0.0f;

    auto issue = [&](int cidx, int buf) {
        const float* Xp = X + (size_t)bm * Dn + cidx * 32;
        const float* Wp = W + (size_t)bn * Dn + cidx * 32;   // Wt[N,K]
        uint32_t abase = sbase + buf * (G_STAGE_F * 4);
        uint32_t bbase = abase + 128 * G_AST * 4;
#pragma unroll
        for (int j = 0; j < 4; j++) {
            int ia = tid + j * 256;
            int r = ia >> 3, cc = ia & 7;
            CP16(abase + r * (G_AST * 4) + cc * 16, Xp + (size_t)r * Dn + cc * 4);
            CP16(bbase + r * (G_AST * 4) + cc * 16, Wp + (size_t)r * Dn + cc * 4);
        }
    };

    issue(0, 0); CP_COMMIT();

    const int NCH = Dn / 32;   // 32
    for (int s = 0; s < NCH; s++) {
        CP_WAIT0();
        __syncthreads();
        if (s + 1 < NCH) { issue(s + 1, (s + 1) & 1); CP_COMMIT(); }

        const float* A = sm + (s & 1) * G_STAGE_F;
        const float* B = A + 128 * G_AST;
#pragma unroll
        for (int kk = 0; kk < 32; kk += 8) {
            uint32_t af[4][4], bf[4][2];
#pragma unroll
            for (int mt = 0; mt < 4; mt++) {
                int r0 = warpM * 64 + mt * 16 + g;
                float2 a0 = *(const float2*)&A[r0 * G_AST + kk + 2 * t];
                float2 a1 = *(const float2*)&A[(r0 + 8) * G_AST + kk + 2 * t];
                af[mt][0] = fbits(a0.x); af[mt][1] = fbits(a1.x);
                af[mt][2] = fbits(a0.y); af[mt][3] = fbits(a1.y);
            }
#pragma unroll
            for (int nt = 0; nt < 4; nt++) {
                int n0 = warpN * 32 + nt * 8 + g;
                float2 bv = *(const float2*)&B[n0 * G_AST + kk + 2 * t];
                bf[nt][0] = fbits(bv.x); bf[nt][1] = fbits(bv.y);
            }
#pragma unroll
            for (int mt = 0; mt < 4; mt++)
#pragma unroll
                for (int nt = 0; nt < 4; nt++)
                    mma_tf32(c[mt][nt], af[mt], bf[nt]);
        }
    }

#pragma unroll
    for (int mt = 0; mt < 4; mt++) {
#pragma unroll
        for (int nt = 0; nt < 4; nt++) {
            int m0 = bm + warpM * 64 + mt * 16 + g;
            int n0 = bn + warpN * 32 + nt * 8 + 2 * t;
#pragma unroll
            for (int half = 0; half < 2; half++) {
                int m = m0 + half * 8;
                float v0 = c[mt][nt][half * 2 + 0] + bias[n0];
                float v1 = c[mt][nt][half * 2 + 1] + bias[n0 + 1];
                if (mode == 0) {
                    out[(size_t)m * Dn + n0] = v0;
                    out[(size_t)m * Dn + n0 + 1] = v1;
                } else {
                    // head layout, d pi-permuted within 8-groups (consumers read raw)
                    int b = m >> 11, sq = m & (Sn - 1);
                    int h = n0 >> 6;
                    int np0 = (n0 & ~7) | pkmap(n0 & 7);
                    int np1 = (n0 & ~7) | pkmap((n0 & 7) + 1);
                    size_t base = (((size_t)b * Hn + h) * Sn + sq) * DHn;
                    out[base + (np0 & 63)] = tf32r(v0);
                    out[base + (np1 & 63)] = tf32r(v1);
                }
            }
        }
    }
}

// ---------------------------------------------------------------------------
// Fused attention, 2 CTAs/SM. Q/K are DH pi-permuted -> LDS.64 QK fragments.
// V is d pi-permuted -> PV output lands pre-permuted for out-proj.
// ---------------------------------------------------------------------------
#define FQ_ST 72
#define FK_ST 72
#define FV_ST 68
#define FP_ST 68
#define F_Q    0                          // 128 x 72
#define F_A    (128 * FQ_ST)              // 64 x 72
#define F_B    (F_A + 64 * FK_ST)         // 64 x 72 (V uses stride 68 within)
#define F_P    (F_B + 64 * FK_ST)         // 128 x 68
#define F_L    (F_P + 128 * FP_ST)        // 128
#define F_INV  (F_L + 128)                // 128
#define FUSED_SMEM ((F_INV + 128) * 4)    // 109,568 bytes

__global__ __launch_bounds__(256, 2) void fused_attn_kernel(
    const float* __restrict__ q, const float* __restrict__ k,
    const float* __restrict__ v, float* __restrict__ attn,
    float* __restrict__ ctx)
{
    extern __shared__ float sm[];
    const int bh = blockIdx.y;
    const int qt = (NQT - 1) - blockIdx.x;   // heavy tiles first
    const int b = bh >> 4, h = bh & 15;

    const int tid = threadIdx.x;
    const int wid = tid >> 5, lane = tid & 31;
    const int g = lane >> 2, t = lane & 3;
    const int warpM = wid & 1, warpN = wid >> 1;   // 2 x 4

    const uint32_t sbase = smem_u32(sm);
    const float* qb = q + ((size_t)bh * Sn + qt * 128) * DHn;
    const float* kbase = k + (size_t)bh * Sn * DHn;
    const float* vbase = v + (size_t)bh * Sn * DHn;
    float* attn_base = attn + ((size_t)bh * Sn + qt * 128) * Sn;

    const int ntiles = 2 * (qt + 1);   // 64-row K/V tiles

    auto issueK = [&](int c, uint32_t bufoff) {
        const float* kb = kbase + (size_t)(c * 64) * DHn;
        uint32_t dst = sbase + bufoff * 4;
#pragma unroll
        for (int j = 0; j < 4; j++) {
            int ia = tid + j * 256;
            int r = ia >> 4, c4 = ia & 15;
            CP16(dst + r * (FK_ST * 4) + c4 * 16, kb + (size_t)r * DHn + c4 * 4);
        }
    };
    auto issueV = [&](int c, uint32_t bufoff) {
        const float* vb = vbase + (size_t)(c * 64) * DHn;
        uint32_t dst = sbase + bufoff * 4;
#pragma unroll
        for (int j = 0; j < 4; j++) {
            int ia = tid + j * 256;
            int r = ia >> 4, c4 = ia & 15;
            CP16(dst + r * (FV_ST * 4) + c4 * 16, vb + (size_t)r * DHn + c4 * 4);
        }
    };

    // Q load + first K tile
    {
        uint32_t qdst = sbase + F_Q * 4;
#pragma unroll
        for (int j = 0; j < 8; j++) {
            int ia = tid + j * 256;
            int r = ia >> 4, c4 = ia & 15;
            CP16(qdst + r * (FQ_ST * 4) + c4 * 16, qb + (size_t)r * DHn + c4 * 4);
        }
        issueK(0, F_A);
        CP_COMMIT();
    }

    // zero-fill causal upper region (overlaps async loads)
    {
        int zc0 = (qt + 1) * 128;
        int nz4 = (Sn - zc0) >> 2;
        if (nz4 > 0) {
            const float4 zz = make_float4(0.f, 0.f, 0.f, 0.f);
            for (int idx = tid; idx < 128 * nz4; idx += 256) {
                int r = idx / nz4, cc = idx - r * nz4;
                *(float4*)(attn_base + (size_t)r * Sn + zc0 + cc * 4) = zz;
            }
        }
    }

    if (tid < 128) sm[F_L + tid] = 0.0f;

    const float* Qs = sm + F_Q;

    // ---------------- Phase 1: row sums of exp(S) ----------------
    float rs[8];
#pragma unroll
    for (int i = 0; i < 8; i++) rs[i] = 0.0f;

    for (int c = 0; c < ntiles; c++) {
        CP_WAIT0();
        __syncthreads();
        if (c + 1 < ntiles) {
            issueK(c + 1, ((c + 1) & 1) ? F_B : F_A);
            CP_COMMIT();
        }

        const float* K = sm + ((c & 1) ? F_B : F_A);
        float cs[4][2][4];
#pragma unroll
        for (int i = 0; i < 4; i++)
#pragma unroll
            for (int j = 0; j < 2; j++)
#pragma unroll
                for (int kk = 0; kk < 4; kk++) cs[i][j][kk] = 0.0f;

#pragma unroll
        for (int kk = 0; kk < 64; kk += 8) {
            uint32_t af[4][4], bf[2][2];
#pragma unroll
            for (int mt = 0; mt < 4; mt++) {
                int r0 = warpM * 64 + mt * 16 + g;
                float2 a0 = *(const float2*)&Qs[r0 * FQ_ST + kk + 2 * t];
                float2 a1 = *(const float2*)&Qs[(r0 + 8) * FQ_ST + kk + 2 * t];
                af[mt][0] = fbits(a0.x); af[mt][1] = fbits(a1.x);
                af[mt][2] = fbits(a0.y); af[mt][3] = fbits(a1.y);
            }
#pragma unroll
            for (int nt = 0; nt < 2; nt++) {
                int n0 = warpN * 16 + nt * 8 + g;
                float2 bv = *(const float2*)&K[n0 * FK_ST + kk + 2 * t];
                bf[nt][0] = fbits(bv.x); bf[nt][1] = fbits(bv.y);
            }
#pragma unroll
            for (int mt = 0; mt < 4; mt++)
#pragma unroll
                for (int nt = 0; nt < 2; nt++)
                    mma_tf32(cs[mt][nt], af[mt], bf[nt]);
        }

        if (c < 2 * qt) {
#pragma unroll
            for (int mt = 0; mt < 4; mt++)
#pragma unroll
                for (int half = 0; half < 2; half++) {
                    float acc = 0.0f;
#pragma unroll
                    for (int nt = 0; nt < 2; nt++) {
                        acc += __expf(cs[mt][nt][half * 2] * SCALE_F);
                        acc += __expf(cs[mt][nt][half * 2 + 1] * SCALE_F);
                    }
                    rs[mt * 2 + half] += acc;
                }
        } else {
#pragma unroll
            for (int mt = 0; mt < 4; mt++)
#pragma unroll
                for (int half = 0; half < 2; half++) {
                    int qi = qt * 128 + warpM * 64 + mt * 16 + g + half * 8;
                    float acc = 0.0f;
#pragma unroll
                    for (int nt = 0; nt < 2; nt++) {
                        int kj = c * 64 + warpN * 16 + nt * 8 + 2 * t;
                        if (kj <= qi)     acc += __expf(cs[mt][nt][half * 2] * SCALE_F);
                        if (kj + 1 <= qi) acc += __expf(cs[mt][nt][half * 2 + 1] * SCALE_F);
                    }
                    rs[mt * 2 + half] += acc;
                }
        }
    }

    // prefetch phase-2 tiles, then reduce row sums
    __syncthreads();
    issueK(0, F_A); CP_COMMIT();
    issueV(0, F_B); CP_COMMIT();

#pragma unroll
    for (int i = 0; i < 8; i++) {
        rs[i] += __shfl_xor_sync(0xffffffffu, rs[i], 1);
        rs[i] += __shfl_xor_sync(0xffffffffu, rs[i], 2);
    }
    if (t == 0) {
#pragma unroll
        for (int i = 0; i < 8; i++) {
            int row = warpM * 64 + (i >> 1) * 16 + g + (i & 1) * 8;
            atomicAdd(&sm[F_L + row], rs[i]);
        }
    }
    __syncthreads();
    if (tid < 128) sm[F_INV + tid] = 1.0f / sm[F_L + tid];
    __syncthreads();

    // ---------------- Phase 2: attn write (coalesced) + P@V ----------------
    float o[4][2][4];
#pragma unroll
    for (int i = 0; i < 4; i++)
#pragma unroll
        for (int j = 0; j < 2; j++)
#pragma unroll
            for (int kk = 0; kk < 4; kk++) o[i][j][kk] = 0.0f;

    float* Ps = sm + F_P;
    const float* invl = sm + F_INV;
    const float* Kb = sm + F_A;
    const float* Vb = sm + F_B;

    const int st_r0 = tid >> 4, st_c = (tid & 15) * 4;

    for (int c = 0; c < ntiles; c++) {
        CP_WAIT1();
        __syncthreads();

        float cs[4][2][4];
#pragma unroll
        for (int i = 0; i < 4; i++)
#pragma unroll
            for (int j = 0; j < 2; j++)
#pragma unroll
                for (int kk = 0; kk < 4; kk++) cs[i][j][kk] = 0.0f;

#pragma unroll
        for (int kk = 0; kk < 64; kk += 8) {
            uint32_t af[4][4], bf[2][2];
#pragma unroll
            for (int mt = 0; mt < 4; mt++) {
                int r0 = warpM * 64 + mt * 16 + g;
                float2 a0 = *(const float2*)&Qs[r0 * FQ_ST + kk + 2 * t];
                float2 a1 = *(const float2*)&Qs[(r0 + 8) * FQ_ST + kk + 2 * t];
                af[mt][0] = fbits(a0.x); af[mt][1] = fbits(a1.x);
                af[mt][2] = fbits(a0.y); af[mt][3] = fbits(a1.y);
            }
#pragma unroll
            for (int nt = 0; nt < 2; nt++) {
                int n0 = warpN * 16 + nt * 8 + g;
                float2 bv = *(const float2*)&Kb[n0 * FK_ST + kk + 2 * t];
                bf[nt][0] = fbits(bv.x); bf[nt][1] = fbits(bv.y);
            }
#pragma unroll
            for (int mt = 0; mt < 4; mt++)
#pragma unroll
                for (int nt = 0; nt < 2; nt++)
                    mma_tf32(cs[mt][nt], af[mt], bf[nt]);
        }

        __syncthreads();
        if (c + 1 < ntiles) { issueK(c + 1, F_A); CP_COMMIT(); }

        // P = round_tf32(exp(S)*inv_l) -> smem Ps (overlaps K(c+1) load)
        if (c < 2 * qt) {
#pragma unroll
            for (int mt = 0; mt < 4; mt++)
#pragma unroll
                for (int half = 0; half < 2; half++) {
                    int rloc = warpM * 64 + mt * 16 + g + half * 8;
                    float inv = invl[rloc];
#pragma unroll
                    for (int nt = 0; nt < 2; nt++) {
                        int klc = warpN * 16 + nt * 8 + 2 * t;
                        float p0 = tf32r(__expf(cs[mt][nt][half * 2] * SCALE_F) * inv);
                        float p1 = tf32r(__expf(cs[mt][nt][half * 2 + 1] * SCALE_F) * inv);
                        *(float2*)&Ps[rloc * FP_ST + klc] = make_float2(p0, p1);
                    }
                }
        } else {
#pragma unroll
            for (int mt = 0; mt < 4; mt++)
#pragma unroll
                for (int half = 0; half < 2; half++) {
                    int rloc = warpM * 64 + mt * 16 + g + half * 8;
                    int qi = qt * 128 + rloc;
                    float inv = invl[rloc];
#pragma unroll
                    for (int nt = 0; nt < 2; nt++) {
                        int klc = warpN * 16 + nt * 8 + 2 * t;
                        int kj = c * 64 + klc;
                        float p0 = (kj <= qi) ? tf32r(__expf(cs[mt][nt][half * 2] * SCALE_F) * inv) : 0.0f;
                        float p1 = (kj + 1 <= qi) ? tf32r(__expf(cs[mt][nt][half * 2 + 1] * SCALE_F) * inv) : 0.0f;
                        *(float2*)&Ps[rloc * FP_ST + klc] = make_float2(p0, p1);
                    }
                }
        }

        // V(c) ready
        if (c + 1 < ntiles) CP_WAIT1(); else CP_WAIT0();
        __syncthreads();   // Ps visible + V ready

        // coalesced attn store from Ps
        {
            float* dst = attn_base + c * 64 + st_c;
#pragma unroll
            for (int j = 0; j < 8; j++) {
                int r = st_r0 + j * 16;
                *(float4*)(dst + (size_t)r * Sn) = *(const float4*)&Ps[r * FP_ST + st_c];
            }
        }

        // O += P @ V
#pragma unroll
        for (int kk = 0; kk < 64; kk += 8) {
            uint32_t af[4][4], bf[2][2];
#pragma unroll
            for (int mt = 0; mt < 4; mt++) {
                int r0 = warpM * 64 + mt * 16 + g;
                af[mt][0] = fbits(Ps[r0 * FP_ST + kk + t]);
                af[mt][1] = fbits(Ps[(r0 + 8) * FP_ST + kk + t]);
                af[mt][2] = fbits(Ps[r0 * FP_ST + kk + t + 4]);
                af[mt][3] = fbits(Ps[(r0 + 8) * FP_ST + kk + t + 4]);
            }
#pragma unroll
            for (int nt = 0; nt < 2; nt++) {
                int n0 = warpN * 16 + nt * 8 + g;
                bf[nt][0] = fbits(Vb[(kk + t) * FV_ST + n0]);
                bf[nt][1] = fbits(Vb[(kk + t + 4) * FV_ST + n0]);
            }
#pragma unroll
            for (int mt = 0; mt < 4; mt++)
#pragma unroll
                for (int nt = 0; nt < 2; nt++)
                    mma_tf32(o[mt][nt], af[mt], bf[nt]);
        }

        __syncthreads();
        if (c + 1 < ntiles) { issueV(c + 1, F_B); CP_COMMIT(); }
    }

    // write O to ctx [B,S,H*DH] (d already pi-permuted via V; out-proj reads raw)
#pragma unroll
    for (int mt = 0; mt < 4; mt++) {
#pragma unroll
        for (int nt = 0; nt < 2; nt++) {
            int s0 = qt * 128 + warpM * 64 + mt * 16 + g;
            int d0 = warpN * 16 + nt * 8 + 2 * t;
#pragma unroll
            for (int half = 0; half < 2; half++) {
                int s = s0 + half * 8;
                size_t base = ((size_t)b * Sn + s) * Dn + h * DHn + d0;
                ctx[base] = tf32r(o[mt][nt][half * 2 + 0]);
                ctx[base + 1] = tf32r(o[mt][nt][half * 2 + 1]);
            }
        }
    }
}

// ---------------------------------------------------------------------------
// Launch
// ---------------------------------------------------------------------------
extern "C" void kernel_launch(void* const* d_in, const int* in_sizes, int n_in,
                              void* d_out, int out_size)
{
    const float* Q  = (const float*)d_in[0];
    const float* K  = (const float*)d_in[1];
    const float* V  = (const float*)d_in[2];
    const float* wq = (const float*)d_in[4];
    const float* bq = (const float*)d_in[5];
    const float* wk = (const float*)d_in[6];
    const float* bk = (const float*)d_in[7];
    const float* wv = (const float*)d_in[8];
    const float* bv = (const float*)d_in[9];
    const float* wo = (const float*)d_in[10];
    const float* bo = (const float*)d_in[11];

    float* out = (float*)d_out;

    float* attn;
    if ((size_t)out_size >= OUT_ELEMS + ATTN_ELEMS) {
        attn = out + OUT_ELEMS;
    } else {
        void* p = nullptr;
        cudaGetSymbolAddress(&p, g_attn_scratch);
        attn = (float*)p;
    }

    float *gq, *gk, *gv, *gctx, *gqc, *gkc, *gvc, *gwc;
    {
        void* p;
        cudaGetSymbolAddress(&p, g_q);   gq   = (float*)p;
        cudaGetSymbolAddress(&p, g_k);   gk   = (float*)p;
        cudaGetSymbolAddress(&p, g_v);   gv   = (float*)p;
        cudaGetSymbolAddress(&p, g_ctx); gctx = (float*)p;
        cudaGetSymbolAddress(&p, g_qc);  gqc  = (float*)p;
        cudaGetSymbolAddress(&p, g_kc);  gkc  = (float*)p;
        cudaGetSymbolAddress(&p, g_vc);  gvc  = (float*)p;
        cudaGetSymbolAddress(&p, g_wc);  gwc  = (float*)p;
    }
    float* wtq = gwc;
    float* wtk = gwc + (size_t)Dn * Dn;
    float* wtv = gwc + 2 * (size_t)Dn * Dn;
    float* wto = gwc + 3 * (size_t)Dn * Dn;

    cudaFuncSetAttribute(tf32_gemm_kernel,
                         cudaFuncAttributeMaxDynamicSharedMemorySize, GEMM_SMEM);
    cudaFuncSetAttribute(fused_attn_kernel,
                         cudaFuncAttributeMaxDynamicSharedMemorySize, FUSED_SMEM);

    // pre-process: round + k-permute inputs; transpose + round + permute weights
    const int n8_big = (Mn * Dn) / 8;      // 1,048,576
    round_perm_kernel<<<(n8_big + 255) / 256, 256>>>(Q, gqc, n8_big);
    round_perm_kernel<<<(n8_big + 255) / 256, 256>>>(K, gkc, n8_big);
    round_perm_kernel<<<(n8_big + 255) / 256, 256>>>(V, gvc, n8_big);
    dim3 tg(Dn / 32, Dn / 32), tb(32, 8);
    wtrans_kernel<<<tg, tb>>>(wq, wtq);
    wtrans_kernel<<<tg, tb>>>(wk, wtk);
    wtrans_kernel<<<tg, tb>>>(wv, wtv);
    wtrans_kernel<<<tg, tb>>>(wo, wto);

    // QKV projections in one launch (grid.z selects which)
    dim3 gqkv(Dn / 128, Mn / 128, 3);   // (8, 64, 3)
    tf32_gemm_kernel<<<gqkv, 256, GEMM_SMEM>>>(
        gqc, gkc, gvc, wtq, wtk, wtv, bq, bk, bv, gq, gk, gv, 1);

    fused_attn_kernel<<<dim3(NQT, BHn), 256, FUSED_SMEM>>>(gq, gk, gv, attn, gctx);

    // output projection
    dim3 go(Dn / 128, Mn / 128, 1);
    tf32_gemm_kernel<<<go, 256, GEMM_SMEM>>>(
        gctx, gctx, gctx, wto, wto, wto, bo, bo, bo, out, out, out, 0);
}